// round 9
// baseline (speedup 1.0000x reference)
#include <cuda_runtime.h>
#include <cuda_bf16.h>

#define BB 128
#define NN 512
#define CF 64
#define LOG2E 1.4426950408889634f

typedef unsigned int u32;
typedef unsigned long long u64;

// ---------------- scratch ----------------
__device__ __align__(16) unsigned short g_h1hi[BB * NN * CF];
__device__ __align__(16) unsigned short g_h1lo[BB * NN * CF];
__device__ __align__(16) float g_diff[BB * NN * CF];
__device__ float g_s1[BB * NN];
__device__ float g_s2[BB * NN];
__device__ u32 g_adjb[NN * 16];

// ---------------- helpers ----------------
__device__ __forceinline__ void ffma2(u64 &d, u64 a, u64 b) {
    asm("fma.rn.f32x2 %0, %1, %2, %0;" : "+l"(d) : "l"(a), "l"(b));
}
__device__ __forceinline__ u64 bcast2(float w) {
    u64 r; u32 u = __float_as_uint(w);
    asm("mov.b64 %0, {%1, %1};" : "=l"(r) : "r"(u));
    return r;
}
__device__ __forceinline__ u64 pack2(float a, float b) {
    u64 r; asm("mov.b64 %0, {%1, %2};" : "=l"(r) : "f"(a), "f"(b));
    return r;
}
__device__ __forceinline__ float2 unpack2(u64 v) {
    float2 r; asm("mov.b64 {%0, %1}, %2;" : "=f"(r.x), "=f"(r.y) : "l"(v));
    return r;
}
// packed bf16x2: hi16 = bf16(vh), lo16 = bf16(vl)
__device__ __forceinline__ u32 cvt2(float vh, float vl) {
    u32 r; asm("cvt.rn.bf16x2.f32 %0, %1, %2;" : "=r"(r) : "f"(vh), "f"(vl));
    return r;
}
__device__ __forceinline__ u32 smem_u32(const void* p) {
    u32 a;
    asm("{ .reg .u64 t; cvta.to.shared.u64 t, %1; cvt.u32.u64 %0, t; }"
        : "=r"(a) : "l"(p));
    return a;
}
// w = bit ? exp2(max(v, 0.2v)) : 0   (v pre-scaled by log2 e)
__device__ __forceinline__ float wcalc(float v, u32 bit) {
    float u = fmaxf(v, 0.2f * v);
    u = bit ? u : -1e38f;
    float e; asm("ex2.approx.f32 %0, %1;" : "=f"(e) : "f"(u));
    return e;
}

#define LDSM4T(r0, r1, r2, r3, addr) \
    asm volatile("ldmatrix.sync.aligned.m8n8.x4.trans.shared.b16 {%0,%1,%2,%3}, [%4];" \
        : "=r"(r0), "=r"(r1), "=r"(r2), "=r"(r3) : "r"(addr))

#define MMA_BF16(d, a0, a1, a2, a3, b0, b1) \
    asm volatile("mma.sync.aligned.m16n8k16.row.col.f32.bf16.bf16.f32 " \
        "{%0,%1,%2,%3}, {%4,%5,%6,%7}, {%8,%9}, {%0,%1,%2,%3};" \
        : "+f"((d)[0]), "+f"((d)[1]), "+f"((d)[2]), "+f"((d)[3]) \
        : "r"(a0), "r"(a1), "r"(a2), "r"(a3), "r"(b0), "r"(b1))

// ---------------------------------------------------------------------------
// Kernel 1: fused prep. Blocks [0,1024): 64-row GEMM tile -> h1 hi/lo, diff,
// s1/s2 (via c1=(W0+W1)@a1 trick, no shuffles). Blocks [1024,1088): adj ballot.
// ---------------------------------------------------------------------------
__global__ __launch_bounds__(256) void gat_prep_kernel(
    const float* __restrict__ x, const float* __restrict__ W,
    const float* __restrict__ a, const int* __restrict__ adj)
{
    if (blockIdx.x >= 1024) {
        // ---- adj -> bitmask role: 64 blocks x 8 rows ----
        int B = blockIdx.x - 1024;
        int w = threadIdx.x >> 5, lane = threadIdx.x & 31;
        int row = B * 8 + w;
        const int* ar = adj + (size_t)row * NN;
        #pragma unroll
        for (int k = 0; k < 16; k++) {
            int v = __ldg(ar + k * 32 + lane);
            u32 m = __ballot_sync(0xffffffffu, v > 0);
            if (lane == 0) g_adjb[row * 16 + k] = m;
        }
        return;
    }

    __shared__ float W0s[CF * CF];
    __shared__ float W1s[CF * CF];
    __shared__ float xs[64 * CF];
    __shared__ float as[128];
    __shared__ float c1s[64];
    __shared__ float c2s[64];

    int t = threadIdx.x;
    for (int idx = t; idx < CF * CF; idx += 256) {
        W0s[idx] = W[idx];
        W1s[idx] = W[CF * CF + idx];
    }
    if (t < 128) as[t] = __ldg(&a[t]);

    int rowBase = blockIdx.x * 64;
    #pragma unroll
    for (int k = 0; k < 4; k++)
        ((float4*)xs)[t + k * 256] =
            ((const float4*)(x + (size_t)rowBase * CF))[t + k * 256];
    __syncthreads();

    // c1 = (W0+W1)@a1 , c2 = (W0+W1)@a2  (threads 0..127)
    if (t < 128) {
        int c = t & 63, sel = t >> 6;
        const float* av = as + sel * 64;
        float s = 0.f;
        #pragma unroll 4
        for (int f = 0; f < 64; f++)
            s += (W0s[c * 64 + f] + W1s[c * 64 + f]) * av[f];
        (sel ? c2s : c1s)[c] = s;
    }

    int f = t & 63, g = t >> 6;
    #pragma unroll 1
    for (int p = 0; p < 2; p++) {
        int rb = g * 16 + p * 8;
        u64 acc0[4] = {0ULL, 0ULL, 0ULL, 0ULL};
        u64 acc1[4] = {0ULL, 0ULL, 0ULL, 0ULL};
        #pragma unroll 4
        for (int c = 0; c < 64; c++) {
            u64 w0p = bcast2(W0s[c * 64 + f]);
            u64 w1p = bcast2(W1s[c * 64 + f]);
            u64 xp[4];
            #pragma unroll
            for (int q = 0; q < 4; q++)
                xp[q] = pack2(xs[(rb + 2 * q) * 64 + c],
                              xs[(rb + 2 * q + 1) * 64 + c]);
            #pragma unroll
            for (int q = 0; q < 4; q++) {
                ffma2(acc0[q], xp[q], w0p);
                ffma2(acc1[q], xp[q], w1p);
            }
        }
        #pragma unroll
        for (int q = 0; q < 4; q++) {
            float2 h0 = unpack2(acc0[q]);
            float2 h1 = unpack2(acc1[q]);
            #pragma unroll
            for (int rr = 0; rr < 2; rr++) {
                float h1v = rr ? h1.y : h1.x;
                float h0v = rr ? h0.y : h0.x;
                int row = rowBase + rb + 2 * q + rr;
                __nv_bfloat16 hb = __float2bfloat16(h1v);
                float hf = __bfloat162float(hb);
                __nv_bfloat16 lb = __float2bfloat16(h1v - hf);
                g_h1hi[(size_t)row * CF + f] = *(unsigned short*)&hb;
                g_h1lo[(size_t)row * CF + f] = *(unsigned short*)&lb;
                g_diff[(size_t)row * CF + f] = h0v - h1v;
            }
        }
    }
    __syncthreads();   // c1s/c2s visible

    // s1/s2 = x @ c1 / x @ c2  (threads 0..127, bank-rotated)
    if (t < 128) {
        int row = t & 63, sel = t >> 6;
        const float* cv = sel ? c2s : c1s;
        float s = 0.f;
        #pragma unroll 4
        for (int k = 0; k < 64; k++) {
            int c = (k + t) & 63;
            s += xs[row * 64 + c] * cv[c];
        }
        (sel ? g_s2 : g_s1)[rowBase + row] = s;
    }
}

// ---------------------------------------------------------------------------
// Kernel 2: HMMA attention. 1 CTA/batch, 512 threads (16 warps). (R8 verbatim)
// ---------------------------------------------------------------------------
#define SM_HHI  0
#define SM_HLO  65536
#define SM_ADJ  131072            // 512 rows x 17 u32 (padded) = 34816 B
#define SM_S1   165888
#define SM_S2   167936
#define SM_BIAS 169984
#define SMEM_SZ 170240

__global__ __launch_bounds__(512) void gat_attn_kernel(
    const float* __restrict__ bias, float* __restrict__ out)
{
    extern __shared__ char smc[];
    int b = blockIdx.x;
    int t = threadIdx.x;
    u32 smb = smem_u32(smc);

    // ---- stage smem ----
    {
        const u32* ghi = (const u32*)g_h1hi + (size_t)b * (NN * CF / 2);
        const u32* glo = (const u32*)g_h1lo + (size_t)b * (NN * CF / 2);
        #pragma unroll
        for (int k = 0; k < 32; k++) {
            int m = t + k * 512;
            int j = m >> 5, f2 = m & 31;
            u32 off = (u32)(j * 128 + (((f2 >> 2) ^ (j & 7)) << 4) + ((f2 & 3) << 2));
            *(u32*)(smc + SM_HHI + off) = ghi[m];
            *(u32*)(smc + SM_HLO + off) = glo[m];
        }
        u32* adjs = (u32*)(smc + SM_ADJ);
        #pragma unroll
        for (int k = 0; k < 16; k++) {
            int m = t + k * 512;
            adjs[(m >> 4) * 17 + (m & 15)] = g_adjb[m];
        }
        ((float*)(smc + SM_S1))[t] = g_s1[b * NN + t] * LOG2E;
        ((float*)(smc + SM_S2))[t] = g_s2[b * NN + t] * LOG2E;
        if (t < 64) ((float*)(smc + SM_BIAS))[t] = bias[t];
    }
    __syncthreads();

    float* s1s = (float*)(smc + SM_S1);
    float* s2s = (float*)(smc + SM_S2);
    u32*  adjs = (u32*)(smc + SM_ADJ);
    float* bs  = (float*)(smc + SM_BIAS);

    int lane = t & 31, w = t >> 5;
    int qid = lane & 3, gid = lane >> 2;
    int klane = lane & 15;
    int nhalf = lane >> 4;
    int k7 = klane & 7;

    u32 hbc[4], lbc[4];
    #pragma unroll
    for (int g = 0; g < 4; g++) {
        u32 csw = (u32)((((g << 1) + nhalf) ^ k7) << 4);
        hbc[g] = smb + SM_HHI + csw;
        lbc[g] = smb + SM_HLO + csw;
    }

    #pragma unroll 1
    for (int ph = 0; ph < 2; ph++) {
        int rbase = ph * 256 + w * 16;
        int r = rbase + gid, r2 = r + 8;
        float s1r = s1s[r], s1r2 = s1s[r2];

        float d[8][4];
        #pragma unroll
        for (int i = 0; i < 8; i++)
            #pragma unroll
            for (int k = 0; k < 4; k++) d[i][k] = 0.f;
        float S1sum = 0.f, S2sum = 0.f;

        #pragma unroll 4
        for (int c = 0; c < 32; c++) {
            int j0 = c << 4;
            float2 p0 = *(const float2*)(s2s + j0 + (qid << 1));
            float2 p1 = *(const float2*)(s2s + j0 + (qid << 1) + 8);
            u32 wr  = adjs[r * 17 + (c >> 1)];
            u32 wr2 = adjs[r2 * 17 + (c >> 1)];
            int sh = ((c & 1) << 4) + (qid << 1);
            u32 br  = wr >> sh;
            u32 br2 = wr2 >> sh;

            float w00 = wcalc(s1r + p0.x, br & 1);
            float w01 = wcalc(s1r + p0.y, (br >> 1) & 1);
            float w08 = wcalc(s1r + p1.x, (br >> 8) & 1);
            float w09 = wcalc(s1r + p1.y, (br >> 9) & 1);
            float w10 = wcalc(s1r2 + p0.x, br2 & 1);
            float w11 = wcalc(s1r2 + p0.y, (br2 >> 1) & 1);
            float w18 = wcalc(s1r2 + p1.x, (br2 >> 8) & 1);
            float w19 = wcalc(s1r2 + p1.y, (br2 >> 9) & 1);

            S1sum += (w00 + w01) + (w08 + w09);
            S2sum += (w10 + w11) + (w18 + w19);

            u32 a0 = cvt2(w01, w00);
            u32 a1 = cvt2(w11, w10);
            u32 a2 = cvt2(w09, w08);
            u32 a3 = cvt2(w19, w18);
            u32 l0 = cvt2(w01 - __uint_as_float(a0 & 0xFFFF0000u),
                          w00 - __uint_as_float(a0 << 16));
            u32 l1 = cvt2(w11 - __uint_as_float(a1 & 0xFFFF0000u),
                          w10 - __uint_as_float(a1 << 16));
            u32 l2 = cvt2(w09 - __uint_as_float(a2 & 0xFFFF0000u),
                          w08 - __uint_as_float(a2 << 16));
            u32 l3 = cvt2(w19 - __uint_as_float(a3 & 0xFFFF0000u),
                          w18 - __uint_as_float(a3 << 16));

            u32 kb = (u32)((j0 + klane) << 7);
            #pragma unroll
            for (int g = 0; g < 4; g++) {
                u32 bh0, bh1, bh2, bh3, bl0, bl1, bl2, bl3;
                LDSM4T(bh0, bh1, bh2, bh3, hbc[g] + kb);
                LDSM4T(bl0, bl1, bl2, bl3, lbc[g] + kb);
                MMA_BF16(d[g * 2],     a0, a1, a2, a3, bh0, bh1);
                MMA_BF16(d[g * 2],     a0, a1, a2, a3, bl0, bl1);
                MMA_BF16(d[g * 2],     l0, l1, l2, l3, bh0, bh1);
                MMA_BF16(d[g * 2 + 1], a0, a1, a2, a3, bh2, bh3);
                MMA_BF16(d[g * 2 + 1], a0, a1, a2, a3, bl2, bl3);
                MMA_BF16(d[g * 2 + 1], l0, l1, l2, l3, bh2, bh3);
            }
        }

        S1sum += __shfl_xor_sync(0xffffffffu, S1sum, 1);
        S1sum += __shfl_xor_sync(0xffffffffu, S1sum, 2);
        S2sum += __shfl_xor_sync(0xffffffffu, S2sum, 1);
        S2sum += __shfl_xor_sync(0xffffffffu, S2sum, 2);

        float dw1 = wcalc(s1r + s2s[r],  (adjs[r * 17 + (r >> 5)] >> (r & 31)) & 1);
        float dw2 = wcalc(s1r2 + s2s[r2], (adjs[r2 * 17 + (r2 >> 5)] >> (r2 & 31)) & 1);

        float inv1 = __fdividef(1.0f, S1sum);
        float inv2 = __fdividef(1.0f, S2sum);
        float wd1 = dw1 * inv1, wd2 = dw2 * inv2;

        const float* dbase = g_diff + (size_t)b * NN * CF;
        float* obase = out + (size_t)b * NN * CF;
        #pragma unroll
        for (int tI = 0; tI < 8; tI++) {
            int nc = tI * 8 + (qid << 1);
            float2 bv = *(const float2*)(bs + nc);
            float2 df1 = __ldg((const float2*)(dbase + (size_t)r * CF + nc));
            float2 df2 = __ldg((const float2*)(dbase + (size_t)r2 * CF + nc));
            float2 o1, o2;
            o1.x = d[tI][0] * inv1 + wd1 * df1.x + bv.x;
            o1.y = d[tI][1] * inv1 + wd1 * df1.y + bv.y;
            o2.x = d[tI][2] * inv2 + wd2 * df2.x + bv.x;
            o2.y = d[tI][3] * inv2 + wd2 * df2.y + bv.y;
            *(float2*)(obase + (size_t)r * CF + nc) = o1;
            *(float2*)(obase + (size_t)r2 * CF + nc) = o2;
        }
    }
}

// ---------------------------------------------------------------------------
extern "C" void kernel_launch(void* const* d_in, const int* in_sizes, int n_in,
                              void* d_out, int out_size) {
    const float* x    = (const float*)d_in[0];
    const int*   adj  = (const int*)d_in[1];
    const float* W    = (const float*)d_in[2];
    const float* a    = (const float*)d_in[3];
    const float* bias = (const float*)d_in[4];
    float* out = (float*)d_out;

    cudaFuncSetAttribute(gat_attn_kernel,
                         cudaFuncAttributeMaxDynamicSharedMemorySize, SMEM_SZ);

    gat_prep_kernel<<<1024 + 64, 256>>>(x, W, a, adj);
    gat_attn_kernel<<<BB, 512, SMEM_SZ>>>(bias, out);
}

// round 10
// speedup vs baseline: 1.1324x; 1.1324x over previous
#include <cuda_runtime.h>
#include <cuda_bf16.h>

#define BB 128
#define NN 512
#define CF 64
#define LOG2E 1.4426950408889634f

typedef unsigned int u32;
typedef unsigned long long u64;

// ---------------- scratch ----------------
__device__ __align__(16) unsigned short g_h1hi[BB * NN * CF];
__device__ __align__(16) unsigned short g_h1lo[BB * NN * CF];
__device__ __align__(16) float g_diff[BB * NN * CF];
__device__ float g_s1[BB * NN];
__device__ float g_s2[BB * NN];
__device__ u32 g_adjb[NN * 16];

// ---------------- helpers ----------------
__device__ __forceinline__ void ffma2(u64 &d, u64 a, u64 b) {
    asm("fma.rn.f32x2 %0, %1, %2, %0;" : "+l"(d) : "l"(a), "l"(b));
}
__device__ __forceinline__ u64 bcast2(float w) {
    u64 r; u32 u = __float_as_uint(w);
    asm("mov.b64 %0, {%1, %1};" : "=l"(r) : "r"(u));
    return r;
}
__device__ __forceinline__ u64 pack2(float a, float b) {
    u64 r; asm("mov.b64 %0, {%1, %2};" : "=l"(r) : "f"(a), "f"(b));
    return r;
}
__device__ __forceinline__ float2 unpack2(u64 v) {
    float2 r; asm("mov.b64 {%0, %1}, %2;" : "=f"(r.x), "=f"(r.y) : "l"(v));
    return r;
}
// packed bf16x2: hi16 = bf16(vh), lo16 = bf16(vl)
__device__ __forceinline__ u32 cvt2(float vh, float vl) {
    u32 r; asm("cvt.rn.bf16x2.f32 %0, %1, %2;" : "=r"(r) : "f"(vh), "f"(vl));
    return r;
}
__device__ __forceinline__ u32 smem_u32(const void* p) {
    u32 a;
    asm("{ .reg .u64 t; cvta.to.shared.u64 t, %1; cvt.u32.u64 %0, t; }"
        : "=r"(a) : "l"(p));
    return a;
}
// w = bit ? exp2(max(v, 0.2v)) : 0   (v pre-scaled by log2 e)
__device__ __forceinline__ float wcalc(float v, u32 bit) {
    float u = fmaxf(v, 0.2f * v);
    u = bit ? u : -1e38f;
    float e; asm("ex2.approx.f32 %0, %1;" : "=f"(e) : "f"(u));
    return e;
}

#define LDSM4T(r0, r1, r2, r3, addr) \
    asm volatile("ldmatrix.sync.aligned.m8n8.x4.trans.shared.b16 {%0,%1,%2,%3}, [%4];" \
        : "=r"(r0), "=r"(r1), "=r"(r2), "=r"(r3) : "r"(addr))

#define MMA_BF16(d, a0, a1, a2, a3, b0, b1) \
    asm volatile("mma.sync.aligned.m16n8k16.row.col.f32.bf16.bf16.f32 " \
        "{%0,%1,%2,%3}, {%4,%5,%6,%7}, {%8,%9}, {%0,%1,%2,%3};" \
        : "+f"((d)[0]), "+f"((d)[1]), "+f"((d)[2]), "+f"((d)[3]) \
        : "r"(a0), "r"(a1), "r"(a2), "r"(a3), "r"(b0), "r"(b1))

// ---------------------------------------------------------------------------
// Kernel 1: fused prep. Blocks [0,1024): 64-row GEMM tile -> h1 hi/lo, diff,
// s1/s2 (c-trick, conflict-free via padded WSp). Blocks [1024,1088): adj ballot.
// ---------------------------------------------------------------------------
__global__ __launch_bounds__(256) void gat_prep_kernel(
    const float* __restrict__ x, const float* __restrict__ W,
    const float* __restrict__ a, const int* __restrict__ adj)
{
    if (blockIdx.x >= 1024) {
        int B = blockIdx.x - 1024;
        int w = threadIdx.x >> 5, lane = threadIdx.x & 31;
        int row = B * 8 + w;
        const int* ar = adj + (size_t)row * NN;
        #pragma unroll
        for (int k = 0; k < 16; k++) {
            int v = __ldg(ar + k * 32 + lane);
            u32 m = __ballot_sync(0xffffffffu, v > 0);
            if (lane == 0) g_adjb[row * 16 + k] = m;
        }
        return;
    }

    __shared__ float W0s[CF * CF];
    __shared__ float W1s[CF * CF];
    __shared__ float WSp[CF * 65];     // (W0+W1), padded stride 65
    __shared__ float xs[64 * CF];
    __shared__ float as[128];
    __shared__ float c1s[64];
    __shared__ float c2s[64];

    int t = threadIdx.x;
    #pragma unroll
    for (int k = 0; k < 16; k++) {
        int idx = t + k * 256;
        float v0 = __ldg(&W[idx]);
        float v1 = __ldg(&W[CF * CF + idx]);
        W0s[idx] = v0;
        W1s[idx] = v1;
        WSp[(idx >> 6) * 65 + (idx & 63)] = v0 + v1;
    }
    if (t < 128) as[t] = __ldg(&a[t]);

    int rowBase = blockIdx.x * 64;
    #pragma unroll
    for (int k = 0; k < 4; k++)
        ((float4*)xs)[t + k * 256] =
            ((const float4*)(x + (size_t)rowBase * CF))[t + k * 256];
    __syncthreads();

    // c1 = (W0+W1)@a1 , c2 = (W0+W1)@a2  (threads 0..127, conflict-free WSp)
    if (t < 128) {
        int c = t & 63, sel = t >> 6;
        const float* av = as + sel * 64;
        const float* wr = WSp + c * 65;
        float s = 0.f;
        #pragma unroll 4
        for (int f = 0; f < 64; f++)
            s += wr[f] * av[f];
        (sel ? c2s : c1s)[c] = s;
    }

    int f = t & 63, g = t >> 6;
    #pragma unroll 1
    for (int p = 0; p < 2; p++) {
        int rb = g * 16 + p * 8;
        u64 acc0[4] = {0ULL, 0ULL, 0ULL, 0ULL};
        u64 acc1[4] = {0ULL, 0ULL, 0ULL, 0ULL};
        #pragma unroll 4
        for (int c = 0; c < 64; c++) {
            u64 w0p = bcast2(W0s[c * 64 + f]);
            u64 w1p = bcast2(W1s[c * 64 + f]);
            u64 xp[4];
            #pragma unroll
            for (int q = 0; q < 4; q++)
                xp[q] = pack2(xs[(rb + 2 * q) * 64 + c],
                              xs[(rb + 2 * q + 1) * 64 + c]);
            #pragma unroll
            for (int q = 0; q < 4; q++) {
                ffma2(acc0[q], xp[q], w0p);
                ffma2(acc1[q], xp[q], w1p);
            }
        }
        #pragma unroll
        for (int q = 0; q < 4; q++) {
            float2 h0 = unpack2(acc0[q]);
            float2 h1 = unpack2(acc1[q]);
            #pragma unroll
            for (int rr = 0; rr < 2; rr++) {
                float h1v = rr ? h1.y : h1.x;
                float h0v = rr ? h0.y : h0.x;
                int row = rowBase + rb + 2 * q + rr;
                __nv_bfloat16 hb = __float2bfloat16(h1v);
                float hf = __bfloat162float(hb);
                __nv_bfloat16 lb = __float2bfloat16(h1v - hf);
                g_h1hi[(size_t)row * CF + f] = *(unsigned short*)&hb;
                g_h1lo[(size_t)row * CF + f] = *(unsigned short*)&lb;
                g_diff[(size_t)row * CF + f] = h0v - h1v;
            }
        }
    }
    __syncthreads();   // c1s/c2s visible

    // s1/s2 = x @ c1 / x @ c2  (threads 0..127, bank-rotated, conflict-free)
    if (t < 128) {
        int row = t & 63, sel = t >> 6;
        const float* cv = sel ? c2s : c1s;
        float s = 0.f;
        #pragma unroll 4
        for (int k = 0; k < 64; k++) {
            int c = (k + t) & 63;
            s += xs[row * 64 + c] * cv[c];
        }
        (sel ? g_s2 : g_s1)[rowBase + row] = s;
    }
}

// ---------------------------------------------------------------------------
// Kernel 2: HMMA attention. 1 CTA/batch, 512 threads (16 warps). (R8 verbatim)
// ---------------------------------------------------------------------------
#define SM_HHI  0
#define SM_HLO  65536
#define SM_ADJ  131072            // 512 rows x 17 u32 (padded) = 34816 B
#define SM_S1   165888
#define SM_S2   167936
#define SM_BIAS 169984
#define SMEM_SZ 170240

__global__ __launch_bounds__(512) void gat_attn_kernel(
    const float* __restrict__ bias, float* __restrict__ out)
{
    extern __shared__ char smc[];
    int b = blockIdx.x;
    int t = threadIdx.x;
    u32 smb = smem_u32(smc);

    // ---- stage smem ----
    {
        const u32* ghi = (const u32*)g_h1hi + (size_t)b * (NN * CF / 2);
        const u32* glo = (const u32*)g_h1lo + (size_t)b * (NN * CF / 2);
        #pragma unroll
        for (int k = 0; k < 32; k++) {
            int m = t + k * 512;
            int j = m >> 5, f2 = m & 31;
            u32 off = (u32)(j * 128 + (((f2 >> 2) ^ (j & 7)) << 4) + ((f2 & 3) << 2));
            *(u32*)(smc + SM_HHI + off) = ghi[m];
            *(u32*)(smc + SM_HLO + off) = glo[m];
        }
        u32* adjs = (u32*)(smc + SM_ADJ);
        #pragma unroll
        for (int k = 0; k < 16; k++) {
            int m = t + k * 512;
            adjs[(m >> 4) * 17 + (m & 15)] = g_adjb[m];
        }
        ((float*)(smc + SM_S1))[t] = g_s1[b * NN + t] * LOG2E;
        ((float*)(smc + SM_S2))[t] = g_s2[b * NN + t] * LOG2E;
        if (t < 64) ((float*)(smc + SM_BIAS))[t] = bias[t];
    }
    __syncthreads();

    float* s1s = (float*)(smc + SM_S1);
    float* s2s = (float*)(smc + SM_S2);
    u32*  adjs = (u32*)(smc + SM_ADJ);
    float* bs  = (float*)(smc + SM_BIAS);

    int lane = t & 31, w = t >> 5;
    int qid = lane & 3, gid = lane >> 2;
    int klane = lane & 15;
    int nhalf = lane >> 4;
    int k7 = klane & 7;

    u32 hbc[4], lbc[4];
    #pragma unroll
    for (int g = 0; g < 4; g++) {
        u32 csw = (u32)((((g << 1) + nhalf) ^ k7) << 4);
        hbc[g] = smb + SM_HHI + csw;
        lbc[g] = smb + SM_HLO + csw;
    }

    #pragma unroll 1
    for (int ph = 0; ph < 2; ph++) {
        int rbase = ph * 256 + w * 16;
        int r = rbase + gid, r2 = r + 8;
        float s1r = s1s[r], s1r2 = s1s[r2];

        float d[8][4];
        #pragma unroll
        for (int i = 0; i < 8; i++)
            #pragma unroll
            for (int k = 0; k < 4; k++) d[i][k] = 0.f;
        float S1sum = 0.f, S2sum = 0.f;

        #pragma unroll 4
        for (int c = 0; c < 32; c++) {
            int j0 = c << 4;
            float2 p0 = *(const float2*)(s2s + j0 + (qid << 1));
            float2 p1 = *(const float2*)(s2s + j0 + (qid << 1) + 8);
            u32 wr  = adjs[r * 17 + (c >> 1)];
            u32 wr2 = adjs[r2 * 17 + (c >> 1)];
            int sh = ((c & 1) << 4) + (qid << 1);
            u32 br  = wr >> sh;
            u32 br2 = wr2 >> sh;

            float w00 = wcalc(s1r + p0.x, br & 1);
            float w01 = wcalc(s1r + p0.y, (br >> 1) & 1);
            float w08 = wcalc(s1r + p1.x, (br >> 8) & 1);
            float w09 = wcalc(s1r + p1.y, (br >> 9) & 1);
            float w10 = wcalc(s1r2 + p0.x, br2 & 1);
            float w11 = wcalc(s1r2 + p0.y, (br2 >> 1) & 1);
            float w18 = wcalc(s1r2 + p1.x, (br2 >> 8) & 1);
            float w19 = wcalc(s1r2 + p1.y, (br2 >> 9) & 1);

            S1sum += (w00 + w01) + (w08 + w09);
            S2sum += (w10 + w11) + (w18 + w19);

            u32 a0 = cvt2(w01, w00);
            u32 a1 = cvt2(w11, w10);
            u32 a2 = cvt2(w09, w08);
            u32 a3 = cvt2(w19, w18);
            u32 l0 = cvt2(w01 - __uint_as_float(a0 & 0xFFFF0000u),
                          w00 - __uint_as_float(a0 << 16));
            u32 l1 = cvt2(w11 - __uint_as_float(a1 & 0xFFFF0000u),
                          w10 - __uint_as_float(a1 << 16));
            u32 l2 = cvt2(w09 - __uint_as_float(a2 & 0xFFFF0000u),
                          w08 - __uint_as_float(a2 << 16));
            u32 l3 = cvt2(w19 - __uint_as_float(a3 & 0xFFFF0000u),
                          w18 - __uint_as_float(a3 << 16));

            u32 kb = (u32)((j0 + klane) << 7);
            #pragma unroll
            for (int g = 0; g < 4; g++) {
                u32 bh0, bh1, bh2, bh3, bl0, bl1, bl2, bl3;
                LDSM4T(bh0, bh1, bh2, bh3, hbc[g] + kb);
                LDSM4T(bl0, bl1, bl2, bl3, lbc[g] + kb);
                MMA_BF16(d[g * 2],     a0, a1, a2, a3, bh0, bh1);
                MMA_BF16(d[g * 2],     a0, a1, a2, a3, bl0, bl1);
                MMA_BF16(d[g * 2],     l0, l1, l2, l3, bh0, bh1);
                MMA_BF16(d[g * 2 + 1], a0, a1, a2, a3, bh2, bh3);
                MMA_BF16(d[g * 2 + 1], a0, a1, a2, a3, bl2, bl3);
                MMA_BF16(d[g * 2 + 1], l0, l1, l2, l3, bh2, bh3);
            }
        }

        S1sum += __shfl_xor_sync(0xffffffffu, S1sum, 1);
        S1sum += __shfl_xor_sync(0xffffffffu, S1sum, 2);
        S2sum += __shfl_xor_sync(0xffffffffu, S2sum, 1);
        S2sum += __shfl_xor_sync(0xffffffffu, S2sum, 2);

        float dw1 = wcalc(s1r + s2s[r],  (adjs[r * 17 + (r >> 5)] >> (r & 31)) & 1);
        float dw2 = wcalc(s1r2 + s2s[r2], (adjs[r2 * 17 + (r2 >> 5)] >> (r2 & 31)) & 1);

        float inv1 = __fdividef(1.0f, S1sum);
        float inv2 = __fdividef(1.0f, S2sum);
        float wd1 = dw1 * inv1, wd2 = dw2 * inv2;

        const float* dbase = g_diff + (size_t)b * NN * CF;
        float* obase = out + (size_t)b * NN * CF;
        #pragma unroll
        for (int tI = 0; tI < 8; tI++) {
            int nc = tI * 8 + (qid << 1);
            float2 bv = *(const float2*)(bs + nc);
            float2 df1 = __ldg((const float2*)(dbase + (size_t)r * CF + nc));
            float2 df2 = __ldg((const float2*)(dbase + (size_t)r2 * CF + nc));
            float2 o1, o2;
            o1.x = d[tI][0] * inv1 + wd1 * df1.x + bv.x;
            o1.y = d[tI][1] * inv1 + wd1 * df1.y + bv.y;
            o2.x = d[tI][2] * inv2 + wd2 * df2.x + bv.x;
            o2.y = d[tI][3] * inv2 + wd2 * df2.y + bv.y;
            *(float2*)(obase + (size_t)r * CF + nc) = o1;
            *(float2*)(obase + (size_t)r2 * CF + nc) = o2;
        }
    }
}

// ---------------------------------------------------------------------------
extern "C" void kernel_launch(void* const* d_in, const int* in_sizes, int n_in,
                              void* d_out, int out_size) {
    const float* x    = (const float*)d_in[0];
    const int*   adj  = (const int*)d_in[1];
    const float* W    = (const float*)d_in[2];
    const float* a    = (const float*)d_in[3];
    const float* bias = (const float*)d_in[4];
    float* out = (float*)d_out;

    cudaFuncSetAttribute(gat_attn_kernel,
                         cudaFuncAttributeMaxDynamicSharedMemorySize, SMEM_SZ);

    gat_prep_kernel<<<1024 + 64, 256>>>(x, W, a, adj);
    gat_attn_kernel<<<BB, 512, SMEM_SZ>>>(bias, out);
}

// round 11
// speedup vs baseline: 1.7323x; 1.5297x over previous
#include <cuda_runtime.h>
#include <cuda_bf16.h>

#define BB 128
#define NN 512
#define CF 64
#define LOG2E 1.4426950408889634f

typedef unsigned int u32;
typedef unsigned long long u64;

// ---------------- scratch ----------------
__device__ u32 g_adjb[NN * 16];

// ---------------- helpers ----------------
__device__ __forceinline__ u32 cvt2(float vh, float vl) {
    u32 r; asm("cvt.rn.bf16x2.f32 %0, %1, %2;" : "=r"(r) : "f"(vh), "f"(vl));
    return r;   // low16 = bf16(vl), high16 = bf16(vh)
}
__device__ __forceinline__ float bflo_f(u32 p) { return __uint_as_float(p << 16); }
__device__ __forceinline__ float bfhi_f(u32 p) { return __uint_as_float(p & 0xFFFF0000u); }
__device__ __forceinline__ u32 smem_u32(const void* p) {
    u32 a;
    asm("{ .reg .u64 t; cvta.to.shared.u64 t, %1; cvt.u32.u64 %0, t; }"
        : "=r"(a) : "l"(p));
    return a;
}
// w = bit ? exp2(max(v, 0.2v)) : 0   (v pre-scaled by log2 e)
__device__ __forceinline__ float wcalc(float v, u32 bit) {
    float u = fmaxf(v, 0.2f * v);
    u = bit ? u : -1e38f;
    float e; asm("ex2.approx.f32 %0, %1;" : "=f"(e) : "f"(u));
    return e;
}

#define LDSM4(r0, r1, r2, r3, addr) \
    asm volatile("ldmatrix.sync.aligned.m8n8.x4.shared.b16 {%0,%1,%2,%3}, [%4];" \
        : "=r"(r0), "=r"(r1), "=r"(r2), "=r"(r3) : "r"(addr))

#define LDSM4T(r0, r1, r2, r3, addr) \
    asm volatile("ldmatrix.sync.aligned.m8n8.x4.trans.shared.b16 {%0,%1,%2,%3}, [%4];" \
        : "=r"(r0), "=r"(r1), "=r"(r2), "=r"(r3) : "r"(addr))

#define MMA_BF16(d, a0, a1, a2, a3, b0, b1) \
    asm volatile("mma.sync.aligned.m16n8k16.row.col.f32.bf16.bf16.f32 " \
        "{%0,%1,%2,%3}, {%4,%5,%6,%7}, {%8,%9}, {%0,%1,%2,%3};" \
        : "+f"((d)[0]), "+f"((d)[1]), "+f"((d)[2]), "+f"((d)[3]) \
        : "r"(a0), "r"(a1), "r"(a2), "r"(a3), "r"(b0), "r"(b1))

// swizzled byte offset within 128B-row layout: row j, 4-byte pair index f2 (0..31)
__device__ __forceinline__ u32 swoff(int j, int f2) {
    return (u32)(j * 128 + ((((f2 >> 2) ^ (j & 7))) << 4) + ((f2 & 3) << 2));
}

// ---------------------------------------------------------------------------
// Kernel 1: adj -> bitmask (proven R8 version)
// ---------------------------------------------------------------------------
__global__ __launch_bounds__(512) void adj_bits_kernel(const int* __restrict__ adj) {
    int row = blockIdx.x;
    int t = threadIdx.x;
    int v = adj[(size_t)row * NN + t];
    u32 m = __ballot_sync(0xffffffffu, v > 0);
    if ((t & 31) == 0) g_adjb[row * 16 + (t >> 5)] = m;
}

// ---------------------------------------------------------------------------
// Kernel 2: fused GEMM + attention. 1 CTA/batch, 512 threads (16 warps).
// Warp w owns rows [32w, 32w+32) for BOTH the x@W GEMM and the attention
// output (diff/s1 stay in registers; h1 bf16 hi/lo written to own rows).
// ---------------------------------------------------------------------------
#define SM_H    0                 // x hi/lo -> h1 hi/lo : 2 x 65536
#define SM_W    131072            // W0hi, W0lo, W1hi, W1lo : 4 x 8192
#define SM_ADJ  163840            // chunk-major: [chunk][row] 16x512 u32
#define SM_S2   196608            // 512 f32 (pre-scaled by LOG2E)
#define SM_AS   198656            // a vector: 128 f32
#define SM_BIAS 199168            // 64 f32
#define SMEM_SZ 199424

__global__ __launch_bounds__(512) void gat_fused_kernel(
    const float* __restrict__ x, const float* __restrict__ W,
    const float* __restrict__ a, const float* __restrict__ bias,
    float* __restrict__ out)
{
    extern __shared__ char smc[];
    int b = blockIdx.x;
    int t = threadIdx.x;
    u32 smb = smem_u32(smc);

    float* s2s = (float*)(smc + SM_S2);
    float* asv = (float*)(smc + SM_AS);
    float* bs  = (float*)(smc + SM_BIAS);
    u32*  adjs = (u32*)(smc + SM_ADJ);

    // ---- stage: x (fp32 -> bf16 hi/lo, swizzled rows), W, adj, a, bias ----
    {
        const float4* xp = (const float4*)(x + (size_t)b * NN * CF);
        #pragma unroll
        for (int k = 0; k < 16; k++) {
            int idx = t + k * 512;            // float4 index 0..8191
            float4 v = __ldg(xp + idx);
            int row = idx >> 4;
            int f2  = (idx & 15) << 1;
            u32 h0 = cvt2(v.y, v.x);
            u32 l0 = cvt2(v.y - bfhi_f(h0), v.x - bflo_f(h0));
            u32 h1 = cvt2(v.w, v.z);
            u32 l1 = cvt2(v.w - bfhi_f(h1), v.z - bflo_f(h1));
            u32 o0 = swoff(row, f2), o1 = swoff(row, f2 + 1);
            *(u32*)(smc + SM_H + o0) = h0;
            *(u32*)(smc + SM_H + 65536 + o0) = l0;
            *(u32*)(smc + SM_H + o1) = h1;
            *(u32*)(smc + SM_H + 65536 + o1) = l1;
        }
        const float4* wp = (const float4*)W;
        #pragma unroll
        for (int k = 0; k < 4; k++) {
            int idx = t + k * 512;            // 0..2047
            float4 v = __ldg(wp + idx);
            int mat = idx >> 10;              // 0 = W0, 1 = W1
            int rem = idx & 1023;
            int c = rem >> 4;
            int f2 = (rem & 15) << 1;
            u32 base = SM_W + mat * 16384;
            u32 h0 = cvt2(v.y, v.x);
            u32 l0 = cvt2(v.y - bfhi_f(h0), v.x - bflo_f(h0));
            u32 h1 = cvt2(v.w, v.z);
            u32 l1 = cvt2(v.w - bfhi_f(h1), v.z - bflo_f(h1));
            u32 o0 = swoff(c, f2), o1 = swoff(c, f2 + 1);
            *(u32*)(smc + base + o0) = h0;
            *(u32*)(smc + base + 8192 + o0) = l0;
            *(u32*)(smc + base + o1) = h1;
            *(u32*)(smc + base + 8192 + o1) = l1;
        }
        #pragma unroll
        for (int k = 0; k < 16; k++)
            adjs[(k << 9) + t] = g_adjb[t * 16 + k];
        if (t < 128) asv[t] = __ldg(&a[t]);
        if (t < 64) bs[t] = __ldg(&bias[t]);
    }
    __syncthreads();

    int lane = t & 31, w = t >> 5;
    int qid = lane & 3, gid = lane >> 2;
    int klane = lane & 15;
    int nhalf = lane >> 4;
    int k7 = klane & 7;
    int cHalf = lane >> 4;

    u32 cswz[4];
    #pragma unroll
    for (int g = 0; g < 4; g++)
        cswz[g] = (u32)(((((g << 1) + nhalf)) ^ k7) << 4);

    // ---------------- phase 1: x@W0, x@W1 via HMMA (3-pass hi/lo) ----------
    u32 diffA[2][8], diffB[2][8];
    float s1reg[2], s1reg2[2];

    #pragma unroll
    for (int rt = 0; rt < 2; rt++) {
        int rbg = w * 32 + rt * 16;
        int rowA = rbg + (lane & 15);
        u32 aBase = smb + SM_H + rowA * 128;
        int r7x = rowA & 7;

        float d0[8][4], d1[8][4];
        #pragma unroll
        for (int i = 0; i < 8; i++)
            #pragma unroll
            for (int e = 0; e < 4; e++) { d0[i][e] = 0.f; d1[i][e] = 0.f; }

        #pragma unroll
        for (int ks = 0; ks < 4; ks++) {
            u32 achunk = (u32)(((2 * ks + cHalf) ^ r7x) << 4);
            u32 ah0, ah1, ah2, ah3, al0, al1, al2, al3;
            LDSM4(ah0, ah1, ah2, ah3, aBase + achunk);
            LDSM4(al0, al1, al2, al3, aBase + 65536 + achunk);
            u32 kb = (u32)((ks * 16 + klane) * 128);
            #pragma unroll
            for (int g = 0; g < 4; g++) {
                u32 cs = cswz[g];
                u32 b0, b1, b2, b3;
                LDSM4T(b0, b1, b2, b3, smb + SM_W + cs + kb);           // W0 hi
                MMA_BF16(d0[2 * g],     ah0, ah1, ah2, ah3, b0, b1);
                MMA_BF16(d0[2 * g + 1], ah0, ah1, ah2, ah3, b2, b3);
                MMA_BF16(d0[2 * g],     al0, al1, al2, al3, b0, b1);
                MMA_BF16(d0[2 * g + 1], al0, al1, al2, al3, b2, b3);
                LDSM4T(b0, b1, b2, b3, smb + SM_W + 8192 + cs + kb);    // W0 lo
                MMA_BF16(d0[2 * g],     ah0, ah1, ah2, ah3, b0, b1);
                MMA_BF16(d0[2 * g + 1], ah0, ah1, ah2, ah3, b2, b3);
                LDSM4T(b0, b1, b2, b3, smb + SM_W + 16384 + cs + kb);   // W1 hi
                MMA_BF16(d1[2 * g],     ah0, ah1, ah2, ah3, b0, b1);
                MMA_BF16(d1[2 * g + 1], ah0, ah1, ah2, ah3, b2, b3);
                MMA_BF16(d1[2 * g],     al0, al1, al2, al3, b0, b1);
                MMA_BF16(d1[2 * g + 1], al0, al1, al2, al3, b2, b3);
                LDSM4T(b0, b1, b2, b3, smb + SM_W + 24576 + cs + kb);   // W1 lo
                MMA_BF16(d1[2 * g],     ah0, ah1, ah2, ah3, b0, b1);
                MMA_BF16(d1[2 * g + 1], ah0, ah1, ah2, ah3, b2, b3);
            }
        }

        // epilogue: s1/s2, diff (regs), h1 bf16 hi/lo -> smem (own rows)
        int r = rbg + gid, r2 = r + 8;
        float s1pA = 0.f, s2pA = 0.f, s1pB = 0.f, s2pB = 0.f;
        #pragma unroll
        for (int tI = 0; tI < 8; tI++) {
            int nc = tI * 8 + (qid << 1);
            float2 a1v = *(const float2*)(asv + nc);
            float2 a2v = *(const float2*)(asv + 64 + nc);
            int f2 = nc >> 1;
            {
                float h0a = d0[tI][0], h0b = d0[tI][1];
                float h1a = d1[tI][0], h1b = d1[tI][1];
                s1pA += (h0a + h1a) * a1v.x + (h0b + h1b) * a1v.y;
                s2pA += (h0a + h1a) * a2v.x + (h0b + h1b) * a2v.y;
                diffA[rt][tI] = cvt2(h0b - h1b, h0a - h1a);
                u32 hp = cvt2(h1b, h1a);
                u32 lp = cvt2(h1b - bfhi_f(hp), h1a - bflo_f(hp));
                u32 o = swoff(r, f2);
                *(u32*)(smc + SM_H + o) = hp;
                *(u32*)(smc + SM_H + 65536 + o) = lp;
            }
            {
                float h0a = d0[tI][2], h0b = d0[tI][3];
                float h1a = d1[tI][2], h1b = d1[tI][3];
                s1pB += (h0a + h1a) * a1v.x + (h0b + h1b) * a1v.y;
                s2pB += (h0a + h1a) * a2v.x + (h0b + h1b) * a2v.y;
                diffB[rt][tI] = cvt2(h0b - h1b, h0a - h1a);
                u32 hp = cvt2(h1b, h1a);
                u32 lp = cvt2(h1b - bfhi_f(hp), h1a - bflo_f(hp));
                u32 o = swoff(r2, f2);
                *(u32*)(smc + SM_H + o) = hp;
                *(u32*)(smc + SM_H + 65536 + o) = lp;
            }
        }
        s1pA += __shfl_xor_sync(0xffffffffu, s1pA, 1);
        s1pA += __shfl_xor_sync(0xffffffffu, s1pA, 2);
        s2pA += __shfl_xor_sync(0xffffffffu, s2pA, 1);
        s2pA += __shfl_xor_sync(0xffffffffu, s2pA, 2);
        s1pB += __shfl_xor_sync(0xffffffffu, s1pB, 1);
        s1pB += __shfl_xor_sync(0xffffffffu, s1pB, 2);
        s2pB += __shfl_xor_sync(0xffffffffu, s2pB, 1);
        s2pB += __shfl_xor_sync(0xffffffffu, s2pB, 2);
        s1reg[rt]  = s1pA * LOG2E;
        s1reg2[rt] = s1pB * LOG2E;
        if (qid == 0) {
            s2s[r]  = s2pA * LOG2E;
            s2s[r2] = s2pB * LOG2E;
        }
    }
    __syncthreads();   // h1 B-tiles + s2 visible to all warps

    // ---------------- phase 2: HMMA attention (R8-proven mainloop) --------
    u32 hbc[4], lbc[4];
    #pragma unroll
    for (int g = 0; g < 4; g++) {
        hbc[g] = smb + SM_H + cswz[g];
        lbc[g] = smb + SM_H + 65536 + cswz[g];
    }

    #pragma unroll
    for (int ph = 0; ph < 2; ph++) {
        int rbase = w * 32 + ph * 16;
        int r = rbase + gid, r2 = r + 8;
        float s1r = s1reg[ph], s1r2 = s1reg2[ph];

        float d[8][4];
        #pragma unroll
        for (int i = 0; i < 8; i++)
            #pragma unroll
            for (int k = 0; k < 4; k++) d[i][k] = 0.f;
        float S1sum = 0.f, S2sum = 0.f;

        #pragma unroll 4
        for (int c = 0; c < 32; c++) {
            int j0 = c << 4;
            float2 p0 = *(const float2*)(s2s + j0 + (qid << 1));
            float2 p1 = *(const float2*)(s2s + j0 + (qid << 1) + 8);
            u32 wr  = adjs[((c >> 1) << 9) + r];
            u32 wr2 = adjs[((c >> 1) << 9) + r2];
            int sh = ((c & 1) << 4) + (qid << 1);
            u32 br  = wr >> sh;
            u32 br2 = wr2 >> sh;

            float w00 = wcalc(s1r + p0.x, br & 1);
            float w01 = wcalc(s1r + p0.y, (br >> 1) & 1);
            float w08 = wcalc(s1r + p1.x, (br >> 8) & 1);
            float w09 = wcalc(s1r + p1.y, (br >> 9) & 1);
            float w10 = wcalc(s1r2 + p0.x, br2 & 1);
            float w11 = wcalc(s1r2 + p0.y, (br2 >> 1) & 1);
            float w18 = wcalc(s1r2 + p1.x, (br2 >> 8) & 1);
            float w19 = wcalc(s1r2 + p1.y, (br2 >> 9) & 1);

            S1sum += (w00 + w01) + (w08 + w09);
            S2sum += (w10 + w11) + (w18 + w19);

            u32 a0 = cvt2(w01, w00);
            u32 a1 = cvt2(w11, w10);
            u32 a2 = cvt2(w09, w08);
            u32 a3 = cvt2(w19, w18);
            u32 l0 = cvt2(w01 - bfhi_f(a0), w00 - bflo_f(a0));
            u32 l1 = cvt2(w11 - bfhi_f(a1), w10 - bflo_f(a1));
            u32 l2 = cvt2(w09 - bfhi_f(a2), w08 - bflo_f(a2));
            u32 l3 = cvt2(w19 - bfhi_f(a3), w18 - bflo_f(a3));

            u32 kb = (u32)((j0 + klane) << 7);
            #pragma unroll
            for (int g = 0; g < 4; g++) {
                u32 bh0, bh1, bh2, bh3, bl0, bl1, bl2, bl3;
                LDSM4T(bh0, bh1, bh2, bh3, hbc[g] + kb);
                LDSM4T(bl0, bl1, bl2, bl3, lbc[g] + kb);
                MMA_BF16(d[g * 2],     a0, a1, a2, a3, bh0, bh1);
                MMA_BF16(d[g * 2],     a0, a1, a2, a3, bl0, bl1);
                MMA_BF16(d[g * 2],     l0, l1, l2, l3, bh0, bh1);
                MMA_BF16(d[g * 2 + 1], a0, a1, a2, a3, bh2, bh3);
                MMA_BF16(d[g * 2 + 1], a0, a1, a2, a3, bl2, bl3);
                MMA_BF16(d[g * 2 + 1], l0, l1, l2, l3, bh2, bh3);
            }
        }

        S1sum += __shfl_xor_sync(0xffffffffu, S1sum, 1);
        S1sum += __shfl_xor_sync(0xffffffffu, S1sum, 2);
        S2sum += __shfl_xor_sync(0xffffffffu, S2sum, 1);
        S2sum += __shfl_xor_sync(0xffffffffu, S2sum, 2);

        float dw1 = wcalc(s1r + s2s[r],   (adjs[((r >> 5) << 9) + r] >> (r & 31)) & 1);
        float dw2 = wcalc(s1r2 + s2s[r2], (adjs[((r2 >> 5) << 9) + r2] >> (r2 & 31)) & 1);

        float inv1 = __fdividef(1.0f, S1sum);
        float inv2 = __fdividef(1.0f, S2sum);
        float wd1 = dw1 * inv1, wd2 = dw2 * inv2;

        float* obase = out + (size_t)b * NN * CF;
        #pragma unroll
        for (int tI = 0; tI < 8; tI++) {
            int nc = tI * 8 + (qid << 1);
            float2 bv = *(const float2*)(bs + nc);
            float df1x = bflo_f(diffA[ph][tI]), df1y = bfhi_f(diffA[ph][tI]);
            float df2x = bflo_f(diffB[ph][tI]), df2y = bfhi_f(diffB[ph][tI]);
            float2 o1, o2;
            o1.x = d[tI][0] * inv1 + wd1 * df1x + bv.x;
            o1.y = d[tI][1] * inv1 + wd1 * df1y + bv.y;
            o2.x = d[tI][2] * inv2 + wd2 * df2x + bv.x;
            o2.y = d[tI][3] * inv2 + wd2 * df2y + bv.y;
            *(float2*)(obase + (size_t)r * CF + nc) = o1;
            *(float2*)(obase + (size_t)r2 * CF + nc) = o2;
        }
    }
}

// ---------------------------------------------------------------------------
extern "C" void kernel_launch(void* const* d_in, const int* in_sizes, int n_in,
                              void* d_out, int out_size) {
    const float* x    = (const float*)d_in[0];
    const int*   adj  = (const int*)d_in[1];
    const float* W    = (const float*)d_in[2];
    const float* a    = (const float*)d_in[3];
    const float* bias = (const float*)d_in[4];
    float* out = (float*)d_out;

    cudaFuncSetAttribute(gat_fused_kernel,
                         cudaFuncAttributeMaxDynamicSharedMemorySize, SMEM_SZ);

    adj_bits_kernel<<<NN, 512>>>(adj);
    gat_fused_kernel<<<BB, 512, SMEM_SZ>>>(x, W, a, bias, out);
}

// round 12
// speedup vs baseline: 2.3556x; 1.3598x over previous
#include <cuda_runtime.h>
#include <cuda_bf16.h>

#define BB 128
#define NN 512
#define CF 64
#define LOG2E 1.4426950408889634f

typedef unsigned int u32;
typedef unsigned long long u64;

// ---------------- scratch ----------------
__device__ u32 g_adjb[NN * 16];

// ---------------- helpers ----------------
__device__ __forceinline__ u32 cvt2(float vh, float vl) {     // bf16x2 pack
    u32 r; asm("cvt.rn.bf16x2.f32 %0, %1, %2;" : "=r"(r) : "f"(vh), "f"(vl));
    return r;
}
__device__ __forceinline__ u32 cvth2(float vh, float vl) {    // f16x2 pack
    u32 r; asm("cvt.rn.f16x2.f32 %0, %1, %2;" : "=r"(r) : "f"(vh), "f"(vl));
    return r;
}
__device__ __forceinline__ float bflo_f(u32 p) { return __uint_as_float(p << 16); }
__device__ __forceinline__ float bfhi_f(u32 p) { return __uint_as_float(p & 0xFFFF0000u); }
__device__ __forceinline__ u32 smem_u32(const void* p) {
    u32 a;
    asm("{ .reg .u64 t; cvta.to.shared.u64 t, %1; cvt.u32.u64 %0, t; }"
        : "=r"(a) : "l"(p));
    return a;
}
// w = bit ? exp2(lrelu(v) - M) : 0   (v pre-scaled by log2 e; M = row bound)
__device__ __forceinline__ float wcalc(float v, u32 bit, float M) {
    float u = fmaxf(v, 0.2f * v) - M;
    u = bit ? u : -1e38f;
    float e; asm("ex2.approx.f32 %0, %1;" : "=f"(e) : "f"(u));
    return e;
}

#define LDSM4(r0, r1, r2, r3, addr) \
    asm volatile("ldmatrix.sync.aligned.m8n8.x4.shared.b16 {%0,%1,%2,%3}, [%4];" \
        : "=r"(r0), "=r"(r1), "=r"(r2), "=r"(r3) : "r"(addr))

#define LDSM4T(r0, r1, r2, r3, addr) \
    asm volatile("ldmatrix.sync.aligned.m8n8.x4.trans.shared.b16 {%0,%1,%2,%3}, [%4];" \
        : "=r"(r0), "=r"(r1), "=r"(r2), "=r"(r3) : "r"(addr))

#define MMA_BF16(d, a0, a1, a2, a3, b0, b1) \
    asm volatile("mma.sync.aligned.m16n8k16.row.col.f32.bf16.bf16.f32 " \
        "{%0,%1,%2,%3}, {%4,%5,%6,%7}, {%8,%9}, {%0,%1,%2,%3};" \
        : "+f"((d)[0]), "+f"((d)[1]), "+f"((d)[2]), "+f"((d)[3]) \
        : "r"(a0), "r"(a1), "r"(a2), "r"(a3), "r"(b0), "r"(b1))

#define MMA_F16(d, a0, a1, a2, a3, b0, b1) \
    asm volatile("mma.sync.aligned.m16n8k16.row.col.f32.f16.f16.f32 " \
        "{%0,%1,%2,%3}, {%4,%5,%6,%7}, {%8,%9}, {%0,%1,%2,%3};" \
        : "+f"((d)[0]), "+f"((d)[1]), "+f"((d)[2]), "+f"((d)[3]) \
        : "r"(a0), "r"(a1), "r"(a2), "r"(a3), "r"(b0), "r"(b1))

// swizzled byte offset within 128B-row layout: row j, 4-byte pair index f2 (0..31)
__device__ __forceinline__ u32 swoff(int j, int f2) {
    return (u32)(j * 128 + ((((f2 >> 2) ^ (j & 7))) << 4) + ((f2 & 3) << 2));
}

// ---------------------------------------------------------------------------
// Kernel 1: adj -> bitmask
// ---------------------------------------------------------------------------
__global__ __launch_bounds__(512) void adj_bits_kernel(const int* __restrict__ adj) {
    int row = blockIdx.x;
    int t = threadIdx.x;
    int v = adj[(size_t)row * NN + t];
    u32 m = __ballot_sync(0xffffffffu, v > 0);
    if ((t & 31) == 0) g_adjb[row * 16 + (t >> 5)] = m;
}

// ---------------------------------------------------------------------------
// Kernel 2: fused GEMM + attention. 1 CTA/batch, 512 threads (16 warps).
// Phase 1: x@W0/W1 bf16 3-pass HMMA (precision for s1/s2). Phase 2: attention
// as 1-pass fp16 HMMA; weights 2^(lrelu(v)-M_i) in (0,1].
// ---------------------------------------------------------------------------
#define SM_H    0                 // x hi/lo (phase1) ; h1 fp16 in first 64KB (phase2)
#define SM_W    131072            // W0hi, W0lo, W1hi, W1lo : 4 x 8192
#define SM_ADJ  163840            // chunk-major: [chunk][row] 16x512 u32
#define SM_S2   196608            // 512 f32 (pre-scaled by LOG2E)
#define SM_AS   198656            // a vector: 128 f32
#define SM_BIAS 199168            // 64 f32
#define SM_WMAX 199424            // 16 f32
#define SMEM_SZ 199488

__global__ __launch_bounds__(512) void gat_fused_kernel(
    const float* __restrict__ x, const float* __restrict__ W,
    const float* __restrict__ a, const float* __restrict__ bias,
    float* __restrict__ out)
{
    extern __shared__ char smc[];
    int b = blockIdx.x;
    int t = threadIdx.x;
    u32 smb = smem_u32(smc);

    float* s2s = (float*)(smc + SM_S2);
    float* asv = (float*)(smc + SM_AS);
    float* bs  = (float*)(smc + SM_BIAS);
    float* wmx = (float*)(smc + SM_WMAX);
    u32*  adjs = (u32*)(smc + SM_ADJ);

    // ---- stage: x (fp32 -> bf16 hi/lo, swizzled rows), W, adj, a, bias ----
    {
        const float4* xp = (const float4*)(x + (size_t)b * NN * CF);
        #pragma unroll
        for (int k = 0; k < 16; k++) {
            int idx = t + k * 512;
            float4 v = __ldg(xp + idx);
            int row = idx >> 4;
            int f2  = (idx & 15) << 1;
            u32 h0 = cvt2(v.y, v.x);
            u32 l0 = cvt2(v.y - bfhi_f(h0), v.x - bflo_f(h0));
            u32 h1 = cvt2(v.w, v.z);
            u32 l1 = cvt2(v.w - bfhi_f(h1), v.z - bflo_f(h1));
            u32 o0 = swoff(row, f2), o1 = swoff(row, f2 + 1);
            *(u32*)(smc + SM_H + o0) = h0;
            *(u32*)(smc + SM_H + 65536 + o0) = l0;
            *(u32*)(smc + SM_H + o1) = h1;
            *(u32*)(smc + SM_H + 65536 + o1) = l1;
        }
        const float4* wp = (const float4*)W;
        #pragma unroll
        for (int k = 0; k < 4; k++) {
            int idx = t + k * 512;
            float4 v = __ldg(wp + idx);
            int mat = idx >> 10;
            int rem = idx & 1023;
            int c = rem >> 4;
            int f2 = (rem & 15) << 1;
            u32 base = SM_W + mat * 16384;
            u32 h0 = cvt2(v.y, v.x);
            u32 l0 = cvt2(v.y - bfhi_f(h0), v.x - bflo_f(h0));
            u32 h1 = cvt2(v.w, v.z);
            u32 l1 = cvt2(v.w - bfhi_f(h1), v.z - bflo_f(h1));
            u32 o0 = swoff(c, f2), o1 = swoff(c, f2 + 1);
            *(u32*)(smc + base + o0) = h0;
            *(u32*)(smc + base + 8192 + o0) = l0;
            *(u32*)(smc + base + o1) = h1;
            *(u32*)(smc + base + 8192 + o1) = l1;
        }
        #pragma unroll
        for (int k = 0; k < 16; k++)
            adjs[(k << 9) + t] = g_adjb[t * 16 + k];
        if (t < 128) asv[t] = __ldg(&a[t]);
        if (t < 64) bs[t] = __ldg(&bias[t]);
    }
    __syncthreads();

    int lane = t & 31, w = t >> 5;
    int qid = lane & 3, gid = lane >> 2;
    int klane = lane & 15;
    int nhalf = lane >> 4;
    int k7 = klane & 7;
    int cHalf = lane >> 4;

    u32 cswz[4];
    #pragma unroll
    for (int g = 0; g < 4; g++)
        cswz[g] = (u32)(((((g << 1) + nhalf)) ^ k7) << 4);

    // ---------------- phase 1: x@W0, x@W1 via HMMA (3-pass hi/lo) ----------
    u32 diffA[2][8], diffB[2][8];
    float s1reg[2], s1reg2[2];

    #pragma unroll
    for (int rt = 0; rt < 2; rt++) {
        int rbg = w * 32 + rt * 16;
        int rowA = rbg + (lane & 15);
        u32 aBase = smb + SM_H + rowA * 128;
        int r7x = rowA & 7;

        float d0[8][4], d1[8][4];
        #pragma unroll
        for (int i = 0; i < 8; i++)
            #pragma unroll
            for (int e = 0; e < 4; e++) { d0[i][e] = 0.f; d1[i][e] = 0.f; }

        #pragma unroll
        for (int ks = 0; ks < 4; ks++) {
            u32 achunk = (u32)(((2 * ks + cHalf) ^ r7x) << 4);
            u32 ah0, ah1, ah2, ah3, al0, al1, al2, al3;
            LDSM4(ah0, ah1, ah2, ah3, aBase + achunk);
            LDSM4(al0, al1, al2, al3, aBase + 65536 + achunk);
            u32 kb = (u32)((ks * 16 + klane) * 128);
            #pragma unroll
            for (int g = 0; g < 4; g++) {
                u32 cs = cswz[g];
                u32 b0, b1, b2, b3;
                LDSM4T(b0, b1, b2, b3, smb + SM_W + cs + kb);           // W0 hi
                MMA_BF16(d0[2 * g],     ah0, ah1, ah2, ah3, b0, b1);
                MMA_BF16(d0[2 * g + 1], ah0, ah1, ah2, ah3, b2, b3);
                MMA_BF16(d0[2 * g],     al0, al1, al2, al3, b0, b1);
                MMA_BF16(d0[2 * g + 1], al0, al1, al2, al3, b2, b3);
                LDSM4T(b0, b1, b2, b3, smb + SM_W + 8192 + cs + kb);    // W0 lo
                MMA_BF16(d0[2 * g],     ah0, ah1, ah2, ah3, b0, b1);
                MMA_BF16(d0[2 * g + 1], ah0, ah1, ah2, ah3, b2, b3);
                LDSM4T(b0, b1, b2, b3, smb + SM_W + 16384 + cs + kb);   // W1 hi
                MMA_BF16(d1[2 * g],     ah0, ah1, ah2, ah3, b0, b1);
                MMA_BF16(d1[2 * g + 1], ah0, ah1, ah2, ah3, b2, b3);
                MMA_BF16(d1[2 * g],     al0, al1, al2, al3, b0, b1);
                MMA_BF16(d1[2 * g + 1], al0, al1, al2, al3, b2, b3);
                LDSM4T(b0, b1, b2, b3, smb + SM_W + 24576 + cs + kb);   // W1 lo
                MMA_BF16(d1[2 * g],     ah0, ah1, ah2, ah3, b0, b1);
                MMA_BF16(d1[2 * g + 1], ah0, ah1, ah2, ah3, b2, b3);
            }
        }

        // epilogue: s1/s2, diff (regs), h1 fp16 -> smem (own rows)
        int r = rbg + gid, r2 = r + 8;
        float s1pA = 0.f, s2pA = 0.f, s1pB = 0.f, s2pB = 0.f;
        #pragma unroll
        for (int tI = 0; tI < 8; tI++) {
            int nc = tI * 8 + (qid << 1);
            float2 a1v = *(const float2*)(asv + nc);
            float2 a2v = *(const float2*)(asv + 64 + nc);
            int f2 = nc >> 1;
            {
                float h0a = d0[tI][0], h0b = d0[tI][1];
                float h1a = d1[tI][0], h1b = d1[tI][1];
                s1pA += (h0a + h1a) * a1v.x + (h0b + h1b) * a1v.y;
                s2pA += (h0a + h1a) * a2v.x + (h0b + h1b) * a2v.y;
                diffA[rt][tI] = cvt2(h0b - h1b, h0a - h1a);
                *(u32*)(smc + SM_H + swoff(r, f2)) = cvth2(h1b, h1a);
            }
            {
                float h0a = d0[tI][2], h0b = d0[tI][3];
                float h1a = d1[tI][2], h1b = d1[tI][3];
                s1pB += (h0a + h1a) * a1v.x + (h0b + h1b) * a1v.y;
                s2pB += (h0a + h1a) * a2v.x + (h0b + h1b) * a2v.y;
                diffB[rt][tI] = cvt2(h0b - h1b, h0a - h1a);
                *(u32*)(smc + SM_H + swoff(r2, f2)) = cvth2(h1b, h1a);
            }
        }
        s1pA += __shfl_xor_sync(0xffffffffu, s1pA, 1);
        s1pA += __shfl_xor_sync(0xffffffffu, s1pA, 2);
        s2pA += __shfl_xor_sync(0xffffffffu, s2pA, 1);
        s2pA += __shfl_xor_sync(0xffffffffu, s2pA, 2);
        s1pB += __shfl_xor_sync(0xffffffffu, s1pB, 1);
        s1pB += __shfl_xor_sync(0xffffffffu, s1pB, 2);
        s2pB += __shfl_xor_sync(0xffffffffu, s2pB, 1);
        s2pB += __shfl_xor_sync(0xffffffffu, s2pB, 2);
        s1reg[rt]  = s1pA * LOG2E;
        s1reg2[rt] = s1pB * LOG2E;
        if (qid == 0) {
            s2s[r]  = s2pA * LOG2E;
            s2s[r2] = s2pB * LOG2E;
        }
    }
    __syncthreads();   // h1 fp16 B-tiles + s2 visible to all warps

    // ---- global max of s2 (for fp16-safe weight scaling) ----
    {
        float m = s2s[t & 511];
        #pragma unroll
        for (int o = 16; o; o >>= 1)
            m = fmaxf(m, __shfl_xor_sync(0xffffffffu, m, o));
        if (lane == 0) wmx[w] = m;
    }
    __syncthreads();
    float maxS2 = wmx[0];
    #pragma unroll
    for (int k = 1; k < 16; k++) maxS2 = fmaxf(maxS2, wmx[k]);

    // ---------------- phase 2: 1-pass fp16 HMMA attention ----------------
    u32 hbc[4];
    #pragma unroll
    for (int g = 0; g < 4; g++)
        hbc[g] = smb + SM_H + cswz[g];

    #pragma unroll
    for (int ph = 0; ph < 2; ph++) {
        int rbase = w * 32 + ph * 16;
        int r = rbase + gid, r2 = r + 8;
        float s1r = s1reg[ph], s1r2 = s1reg2[ph];
        float vm1 = s1r + maxS2, vm2 = s1r2 + maxS2;
        float M1 = fmaxf(vm1, 0.2f * vm1);
        float M2 = fmaxf(vm2, 0.2f * vm2);

        float d[8][4];
        #pragma unroll
        for (int i = 0; i < 8; i++)
            #pragma unroll
            for (int k = 0; k < 4; k++) d[i][k] = 0.f;
        float S1sum = 0.f, S2sum = 0.f;

        #pragma unroll 4
        for (int c = 0; c < 32; c++) {
            int j0 = c << 4;
            float2 p0 = *(const float2*)(s2s + j0 + (qid << 1));
            float2 p1 = *(const float2*)(s2s + j0 + (qid << 1) + 8);
            u32 wr  = adjs[((c >> 1) << 9) + r];
            u32 wr2 = adjs[((c >> 1) << 9) + r2];
            int sh = ((c & 1) << 4) + (qid << 1);
            u32 br  = wr >> sh;
            u32 br2 = wr2 >> sh;

            float w00 = wcalc(s1r + p0.x, br & 1, M1);
            float w01 = wcalc(s1r + p0.y, (br >> 1) & 1, M1);
            float w08 = wcalc(s1r + p1.x, (br >> 8) & 1, M1);
            float w09 = wcalc(s1r + p1.y, (br >> 9) & 1, M1);
            float w10 = wcalc(s1r2 + p0.x, br2 & 1, M2);
            float w11 = wcalc(s1r2 + p0.y, (br2 >> 1) & 1, M2);
            float w18 = wcalc(s1r2 + p1.x, (br2 >> 8) & 1, M2);
            float w19 = wcalc(s1r2 + p1.y, (br2 >> 9) & 1, M2);

            S1sum += (w00 + w01) + (w08 + w09);
            S2sum += (w10 + w11) + (w18 + w19);

            u32 a0 = cvth2(w01, w00);
            u32 a1 = cvth2(w11, w10);
            u32 a2 = cvth2(w09, w08);
            u32 a3 = cvth2(w19, w18);

            u32 kb = (u32)((j0 + klane) << 7);
            #pragma unroll
            for (int g = 0; g < 4; g++) {
                u32 bh0, bh1, bh2, bh3;
                LDSM4T(bh0, bh1, bh2, bh3, hbc[g] + kb);
                MMA_F16(d[g * 2],     a0, a1, a2, a3, bh0, bh1);
                MMA_F16(d[g * 2 + 1], a0, a1, a2, a3, bh2, bh3);
            }
        }

        S1sum += __shfl_xor_sync(0xffffffffu, S1sum, 1);
        S1sum += __shfl_xor_sync(0xffffffffu, S1sum, 2);
        S2sum += __shfl_xor_sync(0xffffffffu, S2sum, 1);
        S2sum += __shfl_xor_sync(0xffffffffu, S2sum, 2);

        float dw1 = wcalc(s1r + s2s[r],   (adjs[((r >> 5) << 9) + r] >> (r & 31)) & 1, M1);
        float dw2 = wcalc(s1r2 + s2s[r2], (adjs[((r2 >> 5) << 9) + r2] >> (r2 & 31)) & 1, M2);

        float inv1 = __fdividef(1.0f, S1sum);
        float inv2 = __fdividef(1.0f, S2sum);
        float wd1 = dw1 * inv1, wd2 = dw2 * inv2;

        float* obase = out + (size_t)b * NN * CF;
        #pragma unroll
        for (int tI = 0; tI < 8; tI++) {
            int nc = tI * 8 + (qid << 1);
            float2 bv = *(const float2*)(bs + nc);
            float df1x = bflo_f(diffA[ph][tI]), df1y = bfhi_f(diffA[ph][tI]);
            float df2x = bflo_f(diffB[ph][tI]), df2y = bfhi_f(diffB[ph][tI]);
            float2 o1, o2;
            o1.x = d[tI][0] * inv1 + wd1 * df1x + bv.x;
            o1.y = d[tI][1] * inv1 + wd1 * df1y + bv.y;
            o2.x = d[tI][2] * inv2 + wd2 * df2x + bv.x;
            o2.y = d[tI][3] * inv2 + wd2 * df2y + bv.y;
            *(float2*)(obase + (size_t)r * CF + nc) = o1;
            *(float2*)(obase + (size_t)r2 * CF + nc) = o2;
        }
    }
}

// ---------------------------------------------------------------------------
extern "C" void kernel_launch(void* const* d_in, const int* in_sizes, int n_in,
                              void* d_out, int out_size) {
    const float* x    = (const float*)d_in[0];
    const int*   adj  = (const int*)d_in[1];
    const float* W    = (const float*)d_in[2];
    const float* a    = (const float*)d_in[3];
    const float* bias = (const float*)d_in[4];
    float* out = (float*)d_out;

    cudaFuncSetAttribute(gat_fused_kernel,
                         cudaFuncAttributeMaxDynamicSharedMemorySize, SMEM_SZ);

    adj_bits_kernel<<<NN, 512>>>(adj);
    gat_fused_kernel<<<BB, 512, SMEM_SZ>>>(x, W, a, bias, out);
}

// round 13
// speedup vs baseline: 2.5864x; 1.0980x over previous
#include <cuda_runtime.h>
#include <cuda_bf16.h>

#define BB 128
#define NN 512
#define CF 64
#define LOG2E 1.4426950408889634f

typedef unsigned int u32;
typedef unsigned long long u64;

// ---------------- scratch ----------------
__device__ u32 g_adjb[NN * 16];

// ---------------- helpers ----------------
__device__ __forceinline__ u32 cvt2(float vh, float vl) {     // bf16x2 pack
    u32 r; asm("cvt.rn.bf16x2.f32 %0, %1, %2;" : "=r"(r) : "f"(vh), "f"(vl));
    return r;
}
__device__ __forceinline__ u32 cvth2(float vh, float vl) {    // f16x2 pack
    u32 r; asm("cvt.rn.f16x2.f32 %0, %1, %2;" : "=r"(r) : "f"(vh), "f"(vl));
    return r;
}
__device__ __forceinline__ u32 ex2h2(u32 x) {                 // packed fp16 2^x
    u32 r; asm("ex2.approx.f16x2 %0, %1;" : "=r"(r) : "r"(x));
    return r;
}
__device__ __forceinline__ float bflo_f(u32 p) { return __uint_as_float(p << 16); }
__device__ __forceinline__ float bfhi_f(u32 p) { return __uint_as_float(p & 0xFFFF0000u); }
__device__ __forceinline__ u32 smem_u32(const void* p) {
    u32 a;
    asm("{ .reg .u64 t; cvta.to.shared.u64 t, %1; cvt.u32.u64 %0, t; }"
        : "=r"(a) : "l"(p));
    return a;
}
// w = bit ? exp2(lrelu(v) - M) : 0   (v pre-scaled by log2 e; M = row bound)
__device__ __forceinline__ float wcalc(float v, u32 bit, float M) {
    float u = fmaxf(v, 0.2f * v) - M;
    u = bit ? u : -1e38f;
    float e; asm("ex2.approx.f32 %0, %1;" : "=f"(e) : "f"(u));
    return e;
}

#define LDSM4(r0, r1, r2, r3, addr) \
    asm volatile("ldmatrix.sync.aligned.m8n8.x4.shared.b16 {%0,%1,%2,%3}, [%4];" \
        : "=r"(r0), "=r"(r1), "=r"(r2), "=r"(r3) : "r"(addr))

#define LDSM4T(r0, r1, r2, r3, addr) \
    asm volatile("ldmatrix.sync.aligned.m8n8.x4.trans.shared.b16 {%0,%1,%2,%3}, [%4];" \
        : "=r"(r0), "=r"(r1), "=r"(r2), "=r"(r3) : "r"(addr))

#define MMA_BF16(d, a0, a1, a2, a3, b0, b1) \
    asm volatile("mma.sync.aligned.m16n8k16.row.col.f32.bf16.bf16.f32 " \
        "{%0,%1,%2,%3}, {%4,%5,%6,%7}, {%8,%9}, {%0,%1,%2,%3};" \
        : "+f"((d)[0]), "+f"((d)[1]), "+f"((d)[2]), "+f"((d)[3]) \
        : "r"(a0), "r"(a1), "r"(a2), "r"(a3), "r"(b0), "r"(b1))

#define MMA_F16(d, a0, a1, a2, a3, b0, b1) \
    asm volatile("mma.sync.aligned.m16n8k16.row.col.f32.f16.f16.f32 " \
        "{%0,%1,%2,%3}, {%4,%5,%6,%7}, {%8,%9}, {%0,%1,%2,%3};" \
        : "+f"((d)[0]), "+f"((d)[1]), "+f"((d)[2]), "+f"((d)[3]) \
        : "r"(a0), "r"(a1), "r"(a2), "r"(a3), "r"(b0), "r"(b1))

// swizzled byte offset within 128B-row layout: row j, 4-byte pair index f2 (0..31)
__device__ __forceinline__ u32 swoff(int j, int f2) {
    return (u32)(j * 128 + ((((f2 >> 2) ^ (j & 7))) << 4) + ((f2 & 3) << 2));
}

// ---------------------------------------------------------------------------
// Kernel 1: adj -> bitmask
// ---------------------------------------------------------------------------
__global__ __launch_bounds__(512) void adj_bits_kernel(const int* __restrict__ adj) {
    int row = blockIdx.x;
    int t = threadIdx.x;
    int v = adj[(size_t)row * NN + t];
    u32 m = __ballot_sync(0xffffffffu, v > 0);
    if ((t & 31) == 0) g_adjb[row * 16 + (t >> 5)] = m;
}

// ---------------------------------------------------------------------------
// Kernel 2: fused GEMM + attention. 1 CTA/batch, 512 threads (16 warps).
// Phase 1: x@W0/W1 bf16 3-pass HMMA. Phase 2: 1-pass fp16 HMMA attention,
// weights via ex2.approx.f16x2, row sums via ones-MMA (no shuffles).
// ---------------------------------------------------------------------------
#define SM_H    0                 // x hi/lo (phase1) ; h1 fp16 in first 64KB (phase2)
#define SM_W    131072            // W0hi, W0lo, W1hi, W1lo : 4 x 8192
#define SM_ADJ  163840            // chunk-major: [chunk][row] 16x512 u32
#define SM_S2   196608            // 512 f32 (pre-scaled by LOG2E)
#define SM_AS   198656            // a vector: 128 f32
#define SM_BIAS 199168            // 64 f32
#define SM_WMAX 199424            // 16 f32
#define SMEM_SZ 199488

__global__ __launch_bounds__(512) void gat_fused_kernel(
    const float* __restrict__ x, const float* __restrict__ W,
    const float* __restrict__ a, const float* __restrict__ bias,
    float* __restrict__ out)
{
    extern __shared__ char smc[];
    int b = blockIdx.x;
    int t = threadIdx.x;
    u32 smb = smem_u32(smc);

    float* s2s = (float*)(smc + SM_S2);
    float* asv = (float*)(smc + SM_AS);
    float* bs  = (float*)(smc + SM_BIAS);
    float* wmx = (float*)(smc + SM_WMAX);
    u32*  adjs = (u32*)(smc + SM_ADJ);

    // ---- stage: x (fp32 -> bf16 hi/lo, swizzled rows), W, adj, a, bias ----
    {
        const float4* xp = (const float4*)(x + (size_t)b * NN * CF);
        #pragma unroll
        for (int k = 0; k < 16; k++) {
            int idx = t + k * 512;
            float4 v = __ldg(xp + idx);
            int row = idx >> 4;
            int f2  = (idx & 15) << 1;
            u32 h0 = cvt2(v.y, v.x);
            u32 l0 = cvt2(v.y - bfhi_f(h0), v.x - bflo_f(h0));
            u32 h1 = cvt2(v.w, v.z);
            u32 l1 = cvt2(v.w - bfhi_f(h1), v.z - bflo_f(h1));
            u32 o0 = swoff(row, f2), o1 = swoff(row, f2 + 1);
            *(u32*)(smc + SM_H + o0) = h0;
            *(u32*)(smc + SM_H + 65536 + o0) = l0;
            *(u32*)(smc + SM_H + o1) = h1;
            *(u32*)(smc + SM_H + 65536 + o1) = l1;
        }
        const float4* wp = (const float4*)W;
        #pragma unroll
        for (int k = 0; k < 4; k++) {
            int idx = t + k * 512;
            float4 v = __ldg(wp + idx);
            int mat = idx >> 10;
            int rem = idx & 1023;
            int c = rem >> 4;
            int f2 = (rem & 15) << 1;
            u32 base = SM_W + mat * 16384;
            u32 h0 = cvt2(v.y, v.x);
            u32 l0 = cvt2(v.y - bfhi_f(h0), v.x - bflo_f(h0));
            u32 h1 = cvt2(v.w, v.z);
            u32 l1 = cvt2(v.w - bfhi_f(h1), v.z - bflo_f(h1));
            u32 o0 = swoff(c, f2), o1 = swoff(c, f2 + 1);
            *(u32*)(smc + base + o0) = h0;
            *(u32*)(smc + base + 8192 + o0) = l0;
            *(u32*)(smc + base + o1) = h1;
            *(u32*)(smc + base + 8192 + o1) = l1;
        }
        #pragma unroll
        for (int k = 0; k < 16; k++)
            adjs[(k << 9) + t] = g_adjb[t * 16 + k];
        if (t < 128) asv[t] = __ldg(&a[t]);
        if (t < 64) bs[t] = __ldg(&bias[t]);
    }
    __syncthreads();

    int lane = t & 31, w = t >> 5;
    int qid = lane & 3, gid = lane >> 2;
    int klane = lane & 15;
    int nhalf = lane >> 4;
    int k7 = klane & 7;
    int cHalf = lane >> 4;

    u32 cswz[4];
    #pragma unroll
    for (int g = 0; g < 4; g++)
        cswz[g] = (u32)(((((g << 1) + nhalf)) ^ k7) << 4);

    // ---------------- phase 1: x@W0, x@W1 via HMMA (3-pass hi/lo) ----------
    u32 diffA[2][8], diffB[2][8];
    float s1reg[2], s1reg2[2];

    #pragma unroll
    for (int rt = 0; rt < 2; rt++) {
        int rbg = w * 32 + rt * 16;
        int rowA = rbg + (lane & 15);
        u32 aBase = smb + SM_H + rowA * 128;
        int r7x = rowA & 7;

        float d0[8][4], d1[8][4];
        #pragma unroll
        for (int i = 0; i < 8; i++)
            #pragma unroll
            for (int e = 0; e < 4; e++) { d0[i][e] = 0.f; d1[i][e] = 0.f; }

        #pragma unroll
        for (int ks = 0; ks < 4; ks++) {
            u32 achunk = (u32)(((2 * ks + cHalf) ^ r7x) << 4);
            u32 ah0, ah1, ah2, ah3, al0, al1, al2, al3;
            LDSM4(ah0, ah1, ah2, ah3, aBase + achunk);
            LDSM4(al0, al1, al2, al3, aBase + 65536 + achunk);
            u32 kb = (u32)((ks * 16 + klane) * 128);
            #pragma unroll
            for (int g = 0; g < 4; g++) {
                u32 cs = cswz[g];
                u32 b0, b1, b2, b3;
                LDSM4T(b0, b1, b2, b3, smb + SM_W + cs + kb);           // W0 hi
                MMA_BF16(d0[2 * g],     ah0, ah1, ah2, ah3, b0, b1);
                MMA_BF16(d0[2 * g + 1], ah0, ah1, ah2, ah3, b2, b3);
                MMA_BF16(d0[2 * g],     al0, al1, al2, al3, b0, b1);
                MMA_BF16(d0[2 * g + 1], al0, al1, al2, al3, b2, b3);
                LDSM4T(b0, b1, b2, b3, smb + SM_W + 8192 + cs + kb);    // W0 lo
                MMA_BF16(d0[2 * g],     ah0, ah1, ah2, ah3, b0, b1);
                MMA_BF16(d0[2 * g + 1], ah0, ah1, ah2, ah3, b2, b3);
                LDSM4T(b0, b1, b2, b3, smb + SM_W + 16384 + cs + kb);   // W1 hi
                MMA_BF16(d1[2 * g],     ah0, ah1, ah2, ah3, b0, b1);
                MMA_BF16(d1[2 * g + 1], ah0, ah1, ah2, ah3, b2, b3);
                MMA_BF16(d1[2 * g],     al0, al1, al2, al3, b0, b1);
                MMA_BF16(d1[2 * g + 1], al0, al1, al2, al3, b2, b3);
                LDSM4T(b0, b1, b2, b3, smb + SM_W + 24576 + cs + kb);   // W1 lo
                MMA_BF16(d1[2 * g],     ah0, ah1, ah2, ah3, b0, b1);
                MMA_BF16(d1[2 * g + 1], ah0, ah1, ah2, ah3, b2, b3);
            }
        }

        // epilogue: s1/s2, diff (regs), h1 fp16 -> smem (own rows)
        int r = rbg + gid, r2 = r + 8;
        float s1pA = 0.f, s2pA = 0.f, s1pB = 0.f, s2pB = 0.f;
        #pragma unroll
        for (int tI = 0; tI < 8; tI++) {
            int nc = tI * 8 + (qid << 1);
            float2 a1v = *(const float2*)(asv + nc);
            float2 a2v = *(const float2*)(asv + 64 + nc);
            int f2 = nc >> 1;
            {
                float h0a = d0[tI][0], h0b = d0[tI][1];
                float h1a = d1[tI][0], h1b = d1[tI][1];
                s1pA += (h0a + h1a) * a1v.x + (h0b + h1b) * a1v.y;
                s2pA += (h0a + h1a) * a2v.x + (h0b + h1b) * a2v.y;
                diffA[rt][tI] = cvt2(h0b - h1b, h0a - h1a);
                *(u32*)(smc + SM_H + swoff(r, f2)) = cvth2(h1b, h1a);
            }
            {
                float h0a = d0[tI][2], h0b = d0[tI][3];
                float h1a = d1[tI][2], h1b = d1[tI][3];
                s1pB += (h0a + h1a) * a1v.x + (h0b + h1b) * a1v.y;
                s2pB += (h0a + h1a) * a2v.x + (h0b + h1b) * a2v.y;
                diffB[rt][tI] = cvt2(h0b - h1b, h0a - h1a);
                *(u32*)(smc + SM_H + swoff(r2, f2)) = cvth2(h1b, h1a);
            }
        }
        s1pA += __shfl_xor_sync(0xffffffffu, s1pA, 1);
        s1pA += __shfl_xor_sync(0xffffffffu, s1pA, 2);
        s2pA += __shfl_xor_sync(0xffffffffu, s2pA, 1);
        s2pA += __shfl_xor_sync(0xffffffffu, s2pA, 2);
        s1pB += __shfl_xor_sync(0xffffffffu, s1pB, 1);
        s1pB += __shfl_xor_sync(0xffffffffu, s1pB, 2);
        s2pB += __shfl_xor_sync(0xffffffffu, s2pB, 1);
        s2pB += __shfl_xor_sync(0xffffffffu, s2pB, 2);
        s1reg[rt]  = s1pA * LOG2E;
        s1reg2[rt] = s1pB * LOG2E;
        if (qid == 0) {
            s2s[r]  = s2pA * LOG2E;
            s2s[r2] = s2pB * LOG2E;
        }
    }
    __syncthreads();   // h1 fp16 B-tiles + s2 visible to all warps

    // ---- global max of s2 (for fp16-safe weight scaling) ----
    {
        float m = s2s[t & 511];
        #pragma unroll
        for (int o = 16; o; o >>= 1)
            m = fmaxf(m, __shfl_xor_sync(0xffffffffu, m, o));
        if (lane == 0) wmx[w] = m;
    }
    __syncthreads();
    float maxS2 = wmx[0];
    #pragma unroll
    for (int k = 1; k < 16; k++) maxS2 = fmaxf(maxS2, wmx[k]);

    // ---------------- phase 2: 1-pass fp16 HMMA attention ----------------
    u32 hbc[4];
    #pragma unroll
    for (int g = 0; g < 4; g++)
        hbc[g] = smb + SM_H + cswz[g];

    const u32 ONES = 0x3C003C00u;   // fp16 (1.0, 1.0)

    #pragma unroll
    for (int ph = 0; ph < 2; ph++) {
        int rbase = w * 32 + ph * 16;
        int r = rbase + gid, r2 = r + 8;
        float s1r = s1reg[ph], s1r2 = s1reg2[ph];
        float vm1 = s1r + maxS2, vm2 = s1r2 + maxS2;
        float M1 = fmaxf(vm1, 0.2f * vm1);
        float M2 = fmaxf(vm2, 0.2f * vm2);
        // u = max(v, 0.2v) - M = max(A + p, B + 0.2p)
        float A1 = s1r - M1,  B1 = 0.2f * s1r - M1;
        float A2 = s1r2 - M2, B2 = 0.2f * s1r2 - M2;

        float d[8][4];
        #pragma unroll
        for (int i = 0; i < 8; i++)
            #pragma unroll
            for (int k = 0; k < 4; k++) d[i][k] = 0.f;
        float dS[4] = {0.f, 0.f, 0.f, 0.f};   // ones-MMA row sums

        #pragma unroll 4
        for (int c = 0; c < 32; c++) {
            int j0 = c << 4;
            float2 p0 = *(const float2*)(s2s + j0 + (qid << 1));
            float2 p1 = *(const float2*)(s2s + j0 + (qid << 1) + 8);
            u32 wr  = adjs[((c >> 1) << 9) + r];
            u32 wr2 = adjs[((c >> 1) << 9) + r2];
            int sh = ((c & 1) << 4) + (qid << 1);
            u32 br  = wr >> sh;
            u32 br2 = wr2 >> sh;

            float q0x = 0.2f * p0.x, q0y = 0.2f * p0.y;
            float q1x = 0.2f * p1.x, q1y = 0.2f * p1.y;

            float u00 = fmaxf(A1 + p0.x, B1 + q0x);
            float u01 = fmaxf(A1 + p0.y, B1 + q0y);
            float u08 = fmaxf(A1 + p1.x, B1 + q1x);
            float u09 = fmaxf(A1 + p1.y, B1 + q1y);
            float u10 = fmaxf(A2 + p0.x, B2 + q0x);
            float u11 = fmaxf(A2 + p0.y, B2 + q0y);
            float u18 = fmaxf(A2 + p1.x, B2 + q1x);
            float u19 = fmaxf(A2 + p1.y, B2 + q1y);

            u00 = (br & 1u)    ? u00 : -1e4f;
            u01 = (br & 2u)    ? u01 : -1e4f;
            u08 = (br & 256u)  ? u08 : -1e4f;
            u09 = (br & 512u)  ? u09 : -1e4f;
            u10 = (br2 & 1u)   ? u10 : -1e4f;
            u11 = (br2 & 2u)   ? u11 : -1e4f;
            u18 = (br2 & 256u) ? u18 : -1e4f;
            u19 = (br2 & 512u) ? u19 : -1e4f;

            u32 a0 = ex2h2(cvth2(u01, u00));
            u32 a1 = ex2h2(cvth2(u11, u10));
            u32 a2 = ex2h2(cvth2(u09, u08));
            u32 a3 = ex2h2(cvth2(u19, u18));

            MMA_F16(dS, a0, a1, a2, a3, ONES, ONES);   // row sums

            u32 kb = (u32)((j0 + klane) << 7);
            #pragma unroll
            for (int g = 0; g < 4; g++) {
                u32 bh0, bh1, bh2, bh3;
                LDSM4T(bh0, bh1, bh2, bh3, hbc[g] + kb);
                MMA_F16(d[g * 2],     a0, a1, a2, a3, bh0, bh1);
                MMA_F16(d[g * 2 + 1], a0, a1, a2, a3, bh2, bh3);
            }
        }

        float S1sum = dS[0];
        float S2sum = dS[2];

        float dw1 = wcalc(s1r + s2s[r],   (adjs[((r >> 5) << 9) + r] >> (r & 31)) & 1, M1);
        float dw2 = wcalc(s1r2 + s2s[r2], (adjs[((r2 >> 5) << 9) + r2] >> (r2 & 31)) & 1, M2);

        float inv1 = __fdividef(1.0f, S1sum);
        float inv2 = __fdividef(1.0f, S2sum);
        float wd1 = dw1 * inv1, wd2 = dw2 * inv2;

        float* obase = out + (size_t)b * NN * CF;
        #pragma unroll
        for (int tI = 0; tI < 8; tI++) {
            int nc = tI * 8 + (qid << 1);
            float2 bv = *(const float2*)(bs + nc);
            float df1x = bflo_f(diffA[ph][tI]), df1y = bfhi_f(diffA[ph][tI]);
            float df2x = bflo_f(diffB[ph][tI]), df2y = bfhi_f(diffB[ph][tI]);
            float2 o1, o2;
            o1.x = d[tI][0] * inv1 + wd1 * df1x + bv.x;
            o1.y = d[tI][1] * inv1 + wd1 * df1y + bv.y;
            o2.x = d[tI][2] * inv2 + wd2 * df2x + bv.x;
            o2.y = d[tI][3] * inv2 + wd2 * df2y + bv.y;
            *(float2*)(obase + (size_t)r * CF + nc) = o1;
            *(float2*)(obase + (size_t)r2 * CF + nc) = o2;
        }
    }
}

// ---------------------------------------------------------------------------
extern "C" void kernel_launch(void* const* d_in, const int* in_sizes, int n_in,
                              void* d_out, int out_size) {
    const float* x    = (const float*)d_in[0];
    const int*   adj  = (const int*)d_in[1];
    const float* W    = (const float*)d_in[2];
    const float* a    = (const float*)d_in[3];
    const float* bias = (const float*)d_in[4];
    float* out = (float*)d_out;

    cudaFuncSetAttribute(gat_fused_kernel,
                         cudaFuncAttributeMaxDynamicSharedMemorySize, SMEM_SZ);

    adj_bits_kernel<<<NN, 512>>>(adj);
    gat_fused_kernel<<<BB, 512, SMEM_SZ>>>(x, W, a, bias, out);
}

// round 14
// speedup vs baseline: 2.7054x; 1.0460x over previous
#include <cuda_runtime.h>
#include <cuda_bf16.h>

#define BB 128
#define NN 512
#define CF 64
#define LOG2E 1.4426950408889634f

typedef unsigned int u32;
typedef unsigned long long u64;

// ---------------- scratch ----------------
__device__ u32 g_adjb[NN * 16];

// ---------------- helpers ----------------
__device__ __forceinline__ u32 cvt2(float vh, float vl) {     // bf16x2 pack
    u32 r; asm("cvt.rn.bf16x2.f32 %0, %1, %2;" : "=r"(r) : "f"(vh), "f"(vl));
    return r;
}
__device__ __forceinline__ u32 cvth2(float vh, float vl) {    // f16x2 pack
    u32 r; asm("cvt.rn.f16x2.f32 %0, %1, %2;" : "=r"(r) : "f"(vh), "f"(vl));
    return r;
}
__device__ __forceinline__ float2 h2f2(u32 p) {               // unpack f16x2 -> 2 f32
    float2 r;
    asm("{.reg .f16 lo, hi;\n\t mov.b32 {lo, hi}, %2;\n\t"
        "cvt.f32.f16 %0, lo;\n\t cvt.f32.f16 %1, hi;}"
        : "=f"(r.x), "=f"(r.y) : "r"(p));
    return r;
}
__device__ __forceinline__ u32 ex2h2(u32 x) {                 // packed fp16 2^x
    u32 r; asm("ex2.approx.f16x2 %0, %1;" : "=r"(r) : "r"(x));
    return r;
}
__device__ __forceinline__ float bflo_f(u32 p) { return __uint_as_float(p << 16); }
__device__ __forceinline__ float bfhi_f(u32 p) { return __uint_as_float(p & 0xFFFF0000u); }
__device__ __forceinline__ u32 smem_u32(const void* p) {
    u32 a;
    asm("{ .reg .u64 t; cvta.to.shared.u64 t, %1; cvt.u32.u64 %0, t; }"
        : "=r"(a) : "l"(p));
    return a;
}
// w = bit ? exp2(lrelu(v) - M) : 0   (v pre-scaled by log2 e; M = row bound)
__device__ __forceinline__ float wcalc(float v, u32 bit, float M) {
    float u = fmaxf(v, 0.2f * v) - M;
    u = bit ? u : -1e38f;
    float e; asm("ex2.approx.f32 %0, %1;" : "=f"(e) : "f"(u));
    return e;
}

#define LDSM4(r0, r1, r2, r3, addr) \
    asm volatile("ldmatrix.sync.aligned.m8n8.x4.shared.b16 {%0,%1,%2,%3}, [%4];" \
        : "=r"(r0), "=r"(r1), "=r"(r2), "=r"(r3) : "r"(addr))

#define LDSM4T(r0, r1, r2, r3, addr) \
    asm volatile("ldmatrix.sync.aligned.m8n8.x4.trans.shared.b16 {%0,%1,%2,%3}, [%4];" \
        : "=r"(r0), "=r"(r1), "=r"(r2), "=r"(r3) : "r"(addr))

#define MMA_F16(d, a0, a1, a2, a3, b0, b1) \
    asm volatile("mma.sync.aligned.m16n8k16.row.col.f32.f16.f16.f32 " \
        "{%0,%1,%2,%3}, {%4,%5,%6,%7}, {%8,%9}, {%0,%1,%2,%3};" \
        : "+f"((d)[0]), "+f"((d)[1]), "+f"((d)[2]), "+f"((d)[3]) \
        : "r"(a0), "r"(a1), "r"(a2), "r"(a3), "r"(b0), "r"(b1))

// swizzled byte offset within 128B-row layout: row j, 4-byte pair index f2 (0..31)
__device__ __forceinline__ u32 swoff(int j, int f2) {
    return (u32)(j * 128 + ((((f2 >> 2) ^ (j & 7))) << 4) + ((f2 & 3) << 2));
}

// ---------------------------------------------------------------------------
// Kernel 1: adj -> bitmask
// ---------------------------------------------------------------------------
__global__ __launch_bounds__(512) void adj_bits_kernel(const int* __restrict__ adj) {
    int row = blockIdx.x;
    int t = threadIdx.x;
    int v = adj[(size_t)row * NN + t];
    u32 m = __ballot_sync(0xffffffffu, v > 0);
    if ((t & 31) == 0) g_adjb[row * 16 + (t >> 5)] = m;
}

// ---------------------------------------------------------------------------
// Kernel 2: fused GEMM + attention. 1 CTA/batch, 512 threads (16 warps).
// Phase 1: hS = x@(W0+W1) fp16 3-pass (for s1/s2), h1 = x@W1 fp16 1-pass;
//          diff = hS - 2*h1. Phase 2: 1-pass fp16 HMMA attention.
// ---------------------------------------------------------------------------
#define SM_H    0                 // x hi/lo (phase1) ; h1 fp16 in first 64KB (phase2)
#define SM_W    131072            // WS_hi, WS_lo, W1 : 3 x 8192
#define SM_ADJ  163840            // chunk-major: [chunk][row] 16x512 u32
#define SM_S2   196608            // 512 f32 (pre-scaled by LOG2E)
#define SM_AS   198656            // a vector: 128 f32
#define SM_BIAS 199168            // 64 f32
#define SM_WMAX 199424            // 16 f32
#define SMEM_SZ 199488

__global__ __launch_bounds__(512) void gat_fused_kernel(
    const float* __restrict__ x, const float* __restrict__ W,
    const float* __restrict__ a, const float* __restrict__ bias,
    float* __restrict__ out)
{
    extern __shared__ char smc[];
    int b = blockIdx.x;
    int t = threadIdx.x;
    u32 smb = smem_u32(smc);

    float* s2s = (float*)(smc + SM_S2);
    float* asv = (float*)(smc + SM_AS);
    float* bs  = (float*)(smc + SM_BIAS);
    float* wmx = (float*)(smc + SM_WMAX);
    u32*  adjs = (u32*)(smc + SM_ADJ);

    // ---- stage: x (fp32 -> fp16 hi/lo, swizzled rows), WS/W1, adj, a, bias --
    {
        const float4* xp = (const float4*)(x + (size_t)b * NN * CF);
        #pragma unroll
        for (int k = 0; k < 16; k++) {
            int idx = t + k * 512;
            float4 v = __ldg(xp + idx);
            int row = idx >> 4;
            int f2  = (idx & 15) << 1;
            u32 h0 = cvth2(v.y, v.x);
            float2 f0 = h2f2(h0);
            u32 l0 = cvth2(v.y - f0.y, v.x - f0.x);
            u32 h1 = cvth2(v.w, v.z);
            float2 f1 = h2f2(h1);
            u32 l1 = cvth2(v.w - f1.y, v.z - f1.x);
            u32 o0 = swoff(row, f2), o1 = swoff(row, f2 + 1);
            *(u32*)(smc + SM_H + o0) = h0;
            *(u32*)(smc + SM_H + 65536 + o0) = l0;
            *(u32*)(smc + SM_H + o1) = h1;
            *(u32*)(smc + SM_H + 65536 + o1) = l1;
        }
        const float4* wp = (const float4*)W;
        #pragma unroll
        for (int k = 0; k < 2; k++) {
            int idx = t + k * 512;           // 0..1023 (W0 float4 index)
            float4 v0 = __ldg(wp + idx);
            float4 v1 = __ldg(wp + 1024 + idx);
            int c = idx >> 4;
            int f2 = (idx & 15) << 1;
            float sx = v0.x + v1.x, sy = v0.y + v1.y;
            float sz = v0.z + v1.z, sw = v0.w + v1.w;
            u32 hs0 = cvth2(sy, sx);
            float2 fs0 = h2f2(hs0);
            u32 ls0 = cvth2(sy - fs0.y, sx - fs0.x);
            u32 hs1 = cvth2(sw, sz);
            float2 fs1 = h2f2(hs1);
            u32 ls1 = cvth2(sw - fs1.y, sz - fs1.x);
            u32 o0 = swoff(c, f2), o1 = swoff(c, f2 + 1);
            *(u32*)(smc + SM_W + o0) = hs0;               // WS hi
            *(u32*)(smc + SM_W + 8192 + o0) = ls0;        // WS lo
            *(u32*)(smc + SM_W + o1) = hs1;
            *(u32*)(smc + SM_W + 8192 + o1) = ls1;
            *(u32*)(smc + SM_W + 16384 + o0) = cvth2(v1.y, v1.x);   // W1
            *(u32*)(smc + SM_W + 16384 + o1) = cvth2(v1.w, v1.z);
        }
        #pragma unroll
        for (int k = 0; k < 16; k++)
            adjs[(k << 9) + t] = g_adjb[t * 16 + k];
        if (t < 128) asv[t] = __ldg(&a[t]);
        if (t < 64) bs[t] = __ldg(&bias[t]);
    }
    __syncthreads();

    int lane = t & 31, w = t >> 5;
    int qid = lane & 3, gid = lane >> 2;
    int klane = lane & 15;
    int nhalf = lane >> 4;
    int k7 = klane & 7;
    int cHalf = lane >> 4;

    u32 cswz[4];
    #pragma unroll
    for (int g = 0; g < 4; g++)
        cswz[g] = (u32)(((((g << 1) + nhalf)) ^ k7) << 4);

    // ---------------- phase 1: hS (3-pass) + h1 (1-pass) fp16 HMMA ---------
    u32 diffA[2][8], diffB[2][8];
    float s1reg[2], s1reg2[2];

    #pragma unroll
    for (int rt = 0; rt < 2; rt++) {
        int rbg = w * 32 + rt * 16;
        int rowA = rbg + (lane & 15);
        u32 aBase = smb + SM_H + rowA * 128;
        int r7x = rowA & 7;

        float d0[8][4], d1[8][4];
        #pragma unroll
        for (int i = 0; i < 8; i++)
            #pragma unroll
            for (int e = 0; e < 4; e++) { d0[i][e] = 0.f; d1[i][e] = 0.f; }

        #pragma unroll
        for (int ks = 0; ks < 4; ks++) {
            u32 achunk = (u32)(((2 * ks + cHalf) ^ r7x) << 4);
            u32 ah0, ah1, ah2, ah3, al0, al1, al2, al3;
            LDSM4(ah0, ah1, ah2, ah3, aBase + achunk);
            LDSM4(al0, al1, al2, al3, aBase + 65536 + achunk);
            u32 kb = (u32)((ks * 16 + klane) * 128);
            #pragma unroll
            for (int g = 0; g < 4; g++) {
                u32 cs = cswz[g];
                u32 b0, b1, b2, b3;
                LDSM4T(b0, b1, b2, b3, smb + SM_W + cs + kb);           // WS hi
                MMA_F16(d0[2 * g],     ah0, ah1, ah2, ah3, b0, b1);
                MMA_F16(d0[2 * g + 1], ah0, ah1, ah2, ah3, b2, b3);
                MMA_F16(d0[2 * g],     al0, al1, al2, al3, b0, b1);
                MMA_F16(d0[2 * g + 1], al0, al1, al2, al3, b2, b3);
                LDSM4T(b0, b1, b2, b3, smb + SM_W + 8192 + cs + kb);    // WS lo
                MMA_F16(d0[2 * g],     ah0, ah1, ah2, ah3, b0, b1);
                MMA_F16(d0[2 * g + 1], ah0, ah1, ah2, ah3, b2, b3);
                LDSM4T(b0, b1, b2, b3, smb + SM_W + 16384 + cs + kb);   // W1
                MMA_F16(d1[2 * g],     ah0, ah1, ah2, ah3, b0, b1);
                MMA_F16(d1[2 * g + 1], ah0, ah1, ah2, ah3, b2, b3);
            }
        }

        // epilogue: s1/s2 from hS, diff = hS - 2*h1 (regs), h1 fp16 -> smem
        int r = rbg + gid, r2 = r + 8;
        float s1pA = 0.f, s2pA = 0.f, s1pB = 0.f, s2pB = 0.f;
        #pragma unroll
        for (int tI = 0; tI < 8; tI++) {
            int nc = tI * 8 + (qid << 1);
            float2 a1v = *(const float2*)(asv + nc);
            float2 a2v = *(const float2*)(asv + 64 + nc);
            int f2 = nc >> 1;
            {
                float hSa = d0[tI][0], hSb = d0[tI][1];
                float h1a = d1[tI][0], h1b = d1[tI][1];
                s1pA += hSa * a1v.x + hSb * a1v.y;
                s2pA += hSa * a2v.x + hSb * a2v.y;
                diffA[rt][tI] = cvt2(hSb - 2.f * h1b, hSa - 2.f * h1a);
                *(u32*)(smc + SM_H + swoff(r, f2)) = cvth2(h1b, h1a);
            }
            {
                float hSa = d0[tI][2], hSb = d0[tI][3];
                float h1a = d1[tI][2], h1b = d1[tI][3];
                s1pB += hSa * a1v.x + hSb * a1v.y;
                s2pB += hSa * a2v.x + hSb * a2v.y;
                diffB[rt][tI] = cvt2(hSb - 2.f * h1b, hSa - 2.f * h1a);
                *(u32*)(smc + SM_H + swoff(r2, f2)) = cvth2(h1b, h1a);
            }
        }
        s1pA += __shfl_xor_sync(0xffffffffu, s1pA, 1);
        s1pA += __shfl_xor_sync(0xffffffffu, s1pA, 2);
        s2pA += __shfl_xor_sync(0xffffffffu, s2pA, 1);
        s2pA += __shfl_xor_sync(0xffffffffu, s2pA, 2);
        s1pB += __shfl_xor_sync(0xffffffffu, s1pB, 1);
        s1pB += __shfl_xor_sync(0xffffffffu, s1pB, 2);
        s2pB += __shfl_xor_sync(0xffffffffu, s2pB, 1);
        s2pB += __shfl_xor_sync(0xffffffffu, s2pB, 2);
        s1reg[rt]  = s1pA * LOG2E;
        s1reg2[rt] = s1pB * LOG2E;
        if (qid == 0) {
            s2s[r]  = s2pA * LOG2E;
            s2s[r2] = s2pB * LOG2E;
        }
    }
    __syncthreads();   // h1 fp16 B-tiles + s2 visible to all warps

    // ---- global max of s2 (for fp16-safe weight scaling) ----
    {
        float m = s2s[t & 511];
        #pragma unroll
        for (int o = 16; o; o >>= 1)
            m = fmaxf(m, __shfl_xor_sync(0xffffffffu, m, o));
        if (lane == 0) wmx[w] = m;
    }
    __syncthreads();
    float maxS2 = wmx[0];
    #pragma unroll
    for (int k = 1; k < 16; k++) maxS2 = fmaxf(maxS2, wmx[k]);

    // ---------------- phase 2: 1-pass fp16 HMMA attention ----------------
    u32 hbc[4];
    #pragma unroll
    for (int g = 0; g < 4; g++)
        hbc[g] = smb + SM_H + cswz[g];

    const u32 ONES = 0x3C003C00u;   // fp16 (1.0, 1.0)

    #pragma unroll
    for (int ph = 0; ph < 2; ph++) {
        int rbase = w * 32 + ph * 16;
        int r = rbase + gid, r2 = r + 8;
        float s1r = s1reg[ph], s1r2 = s1reg2[ph];
        float vm1 = s1r + maxS2, vm2 = s1r2 + maxS2;
        float M1 = fmaxf(vm1, 0.2f * vm1);
        float M2 = fmaxf(vm2, 0.2f * vm2);
        float A1 = s1r - M1,  B1 = 0.2f * s1r - M1;
        float A2 = s1r2 - M2, B2 = 0.2f * s1r2 - M2;

        float d[8][4];
        #pragma unroll
        for (int i = 0; i < 8; i++)
            #pragma unroll
            for (int k = 0; k < 4; k++) d[i][k] = 0.f;
        float dS[4] = {0.f, 0.f, 0.f, 0.f};

        #pragma unroll 4
        for (int c = 0; c < 32; c++) {
            int j0 = c << 4;
            float2 p0 = *(const float2*)(s2s + j0 + (qid << 1));
            float2 p1 = *(const float2*)(s2s + j0 + (qid << 1) + 8);
            u32 wr  = adjs[((c >> 1) << 9) + r];
            u32 wr2 = adjs[((c >> 1) << 9) + r2];
            int sh = ((c & 1) << 4) + (qid << 1);
            u32 br  = wr >> sh;
            u32 br2 = wr2 >> sh;

            float q0x = 0.2f * p0.x, q0y = 0.2f * p0.y;
            float q1x = 0.2f * p1.x, q1y = 0.2f * p1.y;

            float u00 = fmaxf(A1 + p0.x, B1 + q0x);
            float u01 = fmaxf(A1 + p0.y, B1 + q0y);
            float u08 = fmaxf(A1 + p1.x, B1 + q1x);
            float u09 = fmaxf(A1 + p1.y, B1 + q1y);
            float u10 = fmaxf(A2 + p0.x, B2 + q0x);
            float u11 = fmaxf(A2 + p0.y, B2 + q0y);
            float u18 = fmaxf(A2 + p1.x, B2 + q1x);
            float u19 = fmaxf(A2 + p1.y, B2 + q1y);

            u00 = (br & 1u)    ? u00 : -1e4f;
            u01 = (br & 2u)    ? u01 : -1e4f;
            u08 = (br & 256u)  ? u08 : -1e4f;
            u09 = (br & 512u)  ? u09 : -1e4f;
            u10 = (br2 & 1u)   ? u10 : -1e4f;
            u11 = (br2 & 2u)   ? u11 : -1e4f;
            u18 = (br2 & 256u) ? u18 : -1e4f;
            u19 = (br2 & 512u) ? u19 : -1e4f;

            u32 a0 = ex2h2(cvth2(u01, u00));
            u32 a1 = ex2h2(cvth2(u11, u10));
            u32 a2 = ex2h2(cvth2(u09, u08));
            u32 a3 = ex2h2(cvth2(u19, u18));

            MMA_F16(dS, a0, a1, a2, a3, ONES, ONES);   // row sums

            u32 kb = (u32)((j0 + klane) << 7);
            #pragma unroll
            for (int g = 0; g < 4; g++) {
                u32 bh0, bh1, bh2, bh3;
                LDSM4T(bh0, bh1, bh2, bh3, hbc[g] + kb);
                MMA_F16(d[g * 2],     a0, a1, a2, a3, bh0, bh1);
                MMA_F16(d[g * 2 + 1], a0, a1, a2, a3, bh2, bh3);
            }
        }

        float S1sum = dS[0];
        float S2sum = dS[2];

        float dw1 = wcalc(s1r + s2s[r],   (adjs[((r >> 5) << 9) + r] >> (r & 31)) & 1, M1);
        float dw2 = wcalc(s1r2 + s2s[r2], (adjs[((r2 >> 5) << 9) + r2] >> (r2 & 31)) & 1, M2);

        float inv1 = __fdividef(1.0f, S1sum);
        float inv2 = __fdividef(1.0f, S2sum);
        float wd1 = dw1 * inv1, wd2 = dw2 * inv2;

        float* obase = out + (size_t)b * NN * CF;
        #pragma unroll
        for (int tI = 0; tI < 8; tI++) {
            int nc = tI * 8 + (qid << 1);
            float2 bv = *(const float2*)(bs + nc);
            float df1x = bflo_f(diffA[ph][tI]), df1y = bfhi_f(diffA[ph][tI]);
            float df2x = bflo_f(diffB[ph][tI]), df2y = bfhi_f(diffB[ph][tI]);
            float2 o1, o2;
            o1.x = d[tI][0] * inv1 + wd1 * df1x + bv.x;
            o1.y = d[tI][1] * inv1 + wd1 * df1y + bv.y;
            o2.x = d[tI][2] * inv2 + wd2 * df2x + bv.x;
            o2.y = d[tI][3] * inv2 + wd2 * df2y + bv.y;
            *(float2*)(obase + (size_t)r * CF + nc) = o1;
            *(float2*)(obase + (size_t)r2 * CF + nc) = o2;
        }
    }
}

// ---------------------------------------------------------------------------
extern "C" void kernel_launch(void* const* d_in, const int* in_sizes, int n_in,
                              void* d_out, int out_size) {
    const float* x    = (const float*)d_in[0];
    const int*   adj  = (const int*)d_in[1];
    const float* W    = (const float*)d_in[2];
    const float* a    = (const float*)d_in[3];
    const float* bias = (const float*)d_in[4];
    float* out = (float*)d_out;

    cudaFuncSetAttribute(gat_fused_kernel,
                         cudaFuncAttributeMaxDynamicSharedMemorySize, SMEM_SZ);

    adj_bits_kernel<<<NN, 512>>>(adj);
    gat_fused_kernel<<<BB, 512, SMEM_SZ>>>(x, W, a, bias, out);
}